// round 12
// baseline (speedup 1.0000x reference)
#include <cuda_runtime.h>
#include <cuda_bf16.h>
#include <cuda_fp16.h>
#include <math.h>
#include <stdint.h>

#define NMAX 100000
#define EMAX 1600000
#define DDIM 128

// ---------------- scratch ----------------
__device__ __half g_h [NMAX * DDIM];
__device__ __half g_u [NMAX * DDIM];
__device__ __half g_v [NMAX * DDIM];
__device__ __nv_bfloat16 g_ahi[NMAX * DDIM];
__device__ __nv_bfloat16 g_alo[NMAX * DDIM];
__device__ __nv_bfloat16 g_wthi[4 * DDIM * DDIM];
__device__ __nv_bfloat16 g_wtlo[4 * DDIM * DDIM];
__device__ float4 g_asrc[NMAX];
__device__ float4 g_adst[NMAX];
__device__ float4 g_ew  [EMAX];
__device__ int g_deg   [NMAX];
__device__ int g_rowptr[NMAX + 1];
__device__ int g_cursor[NMAX];
__device__ int g_col   [EMAX];
__device__ int g_bsums [1024];

__device__ __forceinline__ uint32_t smem_to_u32(const void* p) {
    uint32_t a;
    asm("{ .reg .u64 t; cvta.to.shared.u64 t, %1; cvt.u32.u64 %0, t; }" : "=r"(a) : "l"(p));
    return a;
}
#define SW128(off) ((off) ^ (((off) >> 3) & 0x70))

#define LDSM4(r0, r1, r2, r3, addr) \
    asm volatile("ldmatrix.sync.aligned.m8n8.x4.shared.b16 {%0,%1,%2,%3}, [%4];" \
        : "=r"(r0), "=r"(r1), "=r"(r2), "=r"(r3) : "r"(addr))

__device__ __forceinline__ void mma16816(float* d, const uint32_t* a, const uint32_t* b) {
    asm volatile(
        "mma.sync.aligned.m16n8k16.row.col.f32.bf16.bf16.f32 "
        "{%0,%1,%2,%3},{%4,%5,%6,%7},{%8,%9},{%0,%1,%2,%3};"
        : "+f"(d[0]), "+f"(d[1]), "+f"(d[2]), "+f"(d[3])
        : "r"(a[0]), "r"(a[1]), "r"(a[2]), "r"(a[3]), "r"(b[0]), "r"(b[1]));
}

// ---------------- setup ----------------
__device__ __forceinline__ void wsplit_one(const float* __restrict__ W,
                                           __nv_bfloat16* __restrict__ hi,
                                           __nv_bfloat16* __restrict__ lo, int i) {
    int nn = i >> 6;
    int kp = (i & 63) * 2;
    float x0 = W[(size_t)kp * 128 + nn];
    float x1 = W[(size_t)(kp + 1) * 128 + nn];
    __nv_bfloat162 h = __floats2bfloat162_rn(x0, x1);
    float r0 = x0 - __bfloat162float(h.x);
    float r1 = x1 - __bfloat162float(h.y);
    __nv_bfloat162 l = __floats2bfloat162_rn(r0, r1);
    reinterpret_cast<__nv_bfloat162*>(hi)[i] = h;
    reinterpret_cast<__nv_bfloat162*>(lo)[i] = l;
}

__global__ void k_setup(const float* __restrict__ W1, const float* __restrict__ W2,
                        const float* __restrict__ lpw1,
                        __nv_bfloat16* __restrict__ wthi, __nv_bfloat16* __restrict__ wtlo,
                        int n) {
    const int WSZ = DDIM * DDIM;
    int i = blockIdx.x * blockDim.x + threadIdx.x;
    if (i < n) g_deg[i] = 0;
    if (i < 8192)       wsplit_one(W1,               wthi + 0 * WSZ, wtlo + 0 * WSZ, i);
    else if (i < 16384) wsplit_one(W2,               wthi + 1 * WSZ, wtlo + 1 * WSZ, i - 8192);
    else if (i < 24576) wsplit_one(lpw1,             wthi + 2 * WSZ, wtlo + 2 * WSZ, i - 16384);
    else if (i < 32768) wsplit_one(lpw1 + 128 * 128, wthi + 3 * WSZ, wtlo + 3 * WSZ, i - 24576);
}

// ---------------- CSR build ----------------
__global__ void k_hist(const int* __restrict__ dst, int e) {
    int i = blockIdx.x * blockDim.x + threadIdx.x;
    if (i < e) atomicAdd(&g_deg[dst[i]], 1);
}
__global__ void k_scan1(int n) {
    __shared__ int ws[32];
    int tid = threadIdx.x;
    int lane = tid & 31, w = tid >> 5;
    int i = blockIdx.x * 1024 + tid;
    int v = (i < n) ? g_deg[i] : 0;
    int x = v;
#pragma unroll
    for (int o = 1; o < 32; o <<= 1) {
        int t = __shfl_up_sync(0xffffffffu, x, o);
        if (lane >= o) x += t;
    }
    if (lane == 31) ws[w] = x;
    __syncthreads();
    if (w == 0) {
        int t = ws[lane];
        int s = t;
#pragma unroll
        for (int o = 1; o < 32; o <<= 1) {
            int q = __shfl_up_sync(0xffffffffu, s, o);
            if (lane >= o) s += q;
        }
        ws[lane] = s - t;
    }
    __syncthreads();
    int incl = x + ws[w];
    if (i < n) g_rowptr[i] = incl - v;
    if (tid == 1023) g_bsums[blockIdx.x] = incl;
}
__global__ void k_scan2(int nb) {
    __shared__ int wsum[4];
    int tid = threadIdx.x;
    int lane = tid & 31, w = tid >> 5;
    int v = (tid < nb) ? g_bsums[tid] : 0;
    int x = v;
#pragma unroll
    for (int o = 1; o < 32; o <<= 1) {
        int t = __shfl_up_sync(0xffffffffu, x, o);
        if (lane >= o) x += t;
    }
    if (lane == 31) wsum[w] = x;
    __syncthreads();
    int add = 0;
#pragma unroll
    for (int j = 0; j < 4; j++) add += (j < w) ? wsum[j] : 0;
    if (tid < nb) g_bsums[tid] = x - v + add;
}
__global__ void k_scan3(int n, int e) {
    int i = blockIdx.x * 1024 + threadIdx.x;
    if (i < n) {
        int v = g_rowptr[i] + g_bsums[blockIdx.x];
        g_rowptr[i] = v;
        g_cursor[i] = v;
    }
    if (i == 0) g_rowptr[n] = e;
}
__global__ void k_scatter(const int* __restrict__ src, const int* __restrict__ dst, int e) {
    int i = blockIdx.x * blockDim.x + threadIdx.x;
    if (i < e) {
        int d = dst[i];
        int slot = atomicAdd(&g_cursor[d], 1);
        g_col[slot] = src[i];
    }
}

// ---------------- HMMA GEMM, block 128x128, warp 32x32, K-chunk 64 ----------
// smem per CTA: 64KB -> 2 CTAs/SM (occ 50%).
#define GEMM_SMEM 65536

__global__ void __launch_bounds__(512, 2) k_gemm_mma(
    const float* __restrict__ Af,
    const __nv_bfloat16* __restrict__ Ahi, const __nv_bfloat16* __restrict__ Alo,
    const __nv_bfloat16* __restrict__ Bhi, const __nv_bfloat16* __restrict__ Blo,
    __half* __restrict__ C,
    const float* __restrict__ a_src, const float* __restrict__ a_dst, int n)
{
    extern __shared__ char smem[];
    __shared__ float sAl[128][4];
    __shared__ float sDl[128][4];
    uint32_t sb = smem_to_u32(smem);
    const uint32_t sAhi = sb;
    const uint32_t sAlo = sb + 16384;
    const uint32_t sBhi = sb + 32768;
    const uint32_t sBlo = sb + 49152;

    int tid = threadIdx.x;
    int wid = tid >> 5, lane = tid & 31;
    int wm = wid & 3, wn = wid >> 2;
    int row0 = blockIdx.x * 128;

    if (tid < 128) {
        *reinterpret_cast<float4*>(&sAl[tid][0]) = make_float4(0.f, 0.f, 0.f, 0.f);
        *reinterpret_cast<float4*>(&sDl[tid][0]) = make_float4(0.f, 0.f, 0.f, 0.f);
    }

    float acc[2][4][4];
#pragma unroll
    for (int i = 0; i < 2; i++)
#pragma unroll
        for (int j = 0; j < 4; j++)
#pragma unroll
            for (int q = 0; q < 4; q++) acc[i][j][q] = 0.f;

    const uint4 zero4 = make_uint4(0, 0, 0, 0);

    for (int kh = 0; kh < 2; kh++) {
        __syncthreads();
        // A chunk: 128 rows x 64 k = 1024 uint4/array; B same. 2 iters each.
#pragma unroll
        for (int t = 0; t < 2; t++) {
            int i = tid + t * 512;
            int r = i >> 3, oo = i & 7;
            uint32_t soff = SW128((uint32_t)(r * 128 + oo * 16));
            size_t elem = (size_t)(row0 + r) * 128 + kh * 64 + oo * 8;
            size_t bidx = ((size_t)r * 128 + kh * 64 + oo * 8) >> 3;
            bool av = (row0 + r) < n;
            uint4 va, vb;
            if (Af) {
                float4 f0 = make_float4(0.f, 0.f, 0.f, 0.f), f1 = f0;
                if (av) {
                    f0 = *reinterpret_cast<const float4*>(&Af[elem]);
                    f1 = *reinterpret_cast<const float4*>(&Af[elem + 4]);
                }
                __nv_bfloat162 h0 = __floats2bfloat162_rn(f0.x, f0.y);
                __nv_bfloat162 h1 = __floats2bfloat162_rn(f0.z, f0.w);
                __nv_bfloat162 h2 = __floats2bfloat162_rn(f1.x, f1.y);
                __nv_bfloat162 h3 = __floats2bfloat162_rn(f1.z, f1.w);
                __nv_bfloat162 l0 = __floats2bfloat162_rn(f0.x - __bfloat162float(h0.x), f0.y - __bfloat162float(h0.y));
                __nv_bfloat162 l1 = __floats2bfloat162_rn(f0.z - __bfloat162float(h1.x), f0.w - __bfloat162float(h1.y));
                __nv_bfloat162 l2 = __floats2bfloat162_rn(f1.x - __bfloat162float(h2.x), f1.y - __bfloat162float(h2.y));
                __nv_bfloat162 l3 = __floats2bfloat162_rn(f1.z - __bfloat162float(h3.x), f1.w - __bfloat162float(h3.y));
                va = make_uint4(*(uint32_t*)&h0, *(uint32_t*)&h1, *(uint32_t*)&h2, *(uint32_t*)&h3);
                vb = make_uint4(*(uint32_t*)&l0, *(uint32_t*)&l1, *(uint32_t*)&l2, *(uint32_t*)&l3);
            } else {
                va = av ? reinterpret_cast<const uint4*>(Ahi)[elem >> 3] : zero4;
                vb = av ? reinterpret_cast<const uint4*>(Alo)[elem >> 3] : zero4;
            }
            *reinterpret_cast<uint4*>(smem + (sAhi - sb) + soff) = va;
            *reinterpret_cast<uint4*>(smem + (sAlo - sb) + soff) = vb;
            *reinterpret_cast<uint4*>(smem + (sBhi - sb) + soff) = reinterpret_cast<const uint4*>(Bhi)[bidx];
            *reinterpret_cast<uint4*>(smem + (sBlo - sb) + soff) = reinterpret_cast<const uint4*>(Blo)[bidx];
        }
        __syncthreads();

#pragma unroll
        for (int kk = 0; kk < 4; kk++) {
            int lr = lane & 15;
            int kin = kk * 16 + ((lane >> 4) << 3);
            uint32_t ahi[2][4], alo[2][4], bxh[2][4], bxl[2][4];
#pragma unroll
            for (int mf = 0; mf < 2; mf++) {
                uint32_t off = SW128((uint32_t)((wm * 32 + mf * 16 + lr) * 128 + kin * 2));
                LDSM4(ahi[mf][0], ahi[mf][1], ahi[mf][2], ahi[mf][3], sAhi + off);
                LDSM4(alo[mf][0], alo[mf][1], alo[mf][2], alo[mf][3], sAlo + off);
            }
#pragma unroll
            for (int nf = 0; nf < 2; nf++) {
                uint32_t off = SW128((uint32_t)((wn * 32 + nf * 16 + lr) * 128 + kin * 2));
                LDSM4(bxh[nf][0], bxh[nf][1], bxh[nf][2], bxh[nf][3], sBhi + off);
                LDSM4(bxl[nf][0], bxl[nf][1], bxl[nf][2], bxl[nf][3], sBlo + off);
            }
#pragma unroll
            for (int mf = 0; mf < 2; mf++) {
#pragma unroll
                for (int ns = 0; ns < 4; ns++) {
                    int g = ns >> 1, od = ns & 1;
                    uint32_t bh[2] = { bxh[g][od], bxh[g][od + 2] };
                    uint32_t bl[2] = { bxl[g][od], bxl[g][od + 2] };
                    mma16816(acc[mf][ns], ahi[mf], bh);
                    mma16816(acc[mf][ns], ahi[mf], bl);
                    mma16816(acc[mf][ns], alo[mf], bh);
                }
            }
        }
    }

    int qrow = lane >> 2, qcol = (lane & 3) * 2;

    // fused alpha partial dots
    {
        float2 s2[4], d2[4];
#pragma unroll
        for (int ns = 0; ns < 4; ns++) {
            int c = wn * 32 + ns * 8 + qcol;
            s2[ns] = *reinterpret_cast<const float2*>(&a_src[c]);
            d2[ns] = *reinterpret_cast<const float2*>(&a_dst[c]);
        }
#pragma unroll
        for (int mf = 0; mf < 2; mf++) {
            int rl = wm * 32 + mf * 16 + qrow;
            float pa0 = 0.f, pd0 = 0.f, pa1 = 0.f, pd1 = 0.f;
#pragma unroll
            for (int ns = 0; ns < 4; ns++) {
                pa0 += acc[mf][ns][0] * s2[ns].x + acc[mf][ns][1] * s2[ns].y;
                pd0 += acc[mf][ns][0] * d2[ns].x + acc[mf][ns][1] * d2[ns].y;
                pa1 += acc[mf][ns][2] * s2[ns].x + acc[mf][ns][3] * s2[ns].y;
                pd1 += acc[mf][ns][2] * d2[ns].x + acc[mf][ns][3] * d2[ns].y;
            }
            atomicAdd(&sAl[rl][wn], pa0);     atomicAdd(&sDl[rl][wn], pd0);
            atomicAdd(&sAl[rl + 8][wn], pa1); atomicAdd(&sDl[rl + 8][wn], pd1);
        }
    }

    // h store as fp16
#pragma unroll
    for (int mf = 0; mf < 2; mf++) {
#pragma unroll
        for (int ns = 0; ns < 4; ns++) {
            int r0 = row0 + wm * 32 + mf * 16 + qrow;
            int c0 = wn * 32 + ns * 8 + qcol;
            if (r0 < n) {
                __half2 hv = __floats2half2_rn(acc[mf][ns][0], acc[mf][ns][1]);
                *reinterpret_cast<uint32_t*>(&C[(size_t)r0 * 128 + c0]) = *(uint32_t*)&hv;
            }
            if (r0 + 8 < n) {
                __half2 hv = __floats2half2_rn(acc[mf][ns][2], acc[mf][ns][3]);
                *reinterpret_cast<uint32_t*>(&C[(size_t)(r0 + 8) * 128 + c0]) = *(uint32_t*)&hv;
            }
        }
    }

    __syncthreads();
    if (tid < 128 && row0 + tid < n) {
        g_asrc[row0 + tid] = *reinterpret_cast<float4*>(&sAl[tid][0]);
        g_adst[row0 + tid] = *reinterpret_cast<float4*>(&sDl[tid][0]);
    }
}

// ---------------- dual-B GEMM: both accumulated per chunk, A loaded once ----
// smem per CTA: 96KB -> 2 CTAs/SM.
#define GEMM2_SMEM 98304

__global__ void __launch_bounds__(512, 2) k_gemm_mma2(
    const __nv_bfloat16* __restrict__ Ahi, const __nv_bfloat16* __restrict__ Alo,
    const __nv_bfloat16* __restrict__ B1hi, const __nv_bfloat16* __restrict__ B1lo,
    const __nv_bfloat16* __restrict__ B2hi, const __nv_bfloat16* __restrict__ B2lo,
    __half* __restrict__ C1, __half* __restrict__ C2, int n)
{
    extern __shared__ char smem[];
    uint32_t sb = smem_to_u32(smem);
    const uint32_t sAhi  = sb;
    const uint32_t sAlo  = sb + 16384;
    const uint32_t sB1hi = sb + 32768;
    const uint32_t sB1lo = sb + 49152;
    const uint32_t sB2hi = sb + 65536;
    const uint32_t sB2lo = sb + 81920;

    int tid = threadIdx.x;
    int wid = tid >> 5, lane = tid & 31;
    int wm = wid & 3, wn = wid >> 2;
    int row0 = blockIdx.x * 128;

    const uint4 zero4 = make_uint4(0, 0, 0, 0);

    float acc1[2][4][4], acc2[2][4][4];
#pragma unroll
    for (int i = 0; i < 2; i++)
#pragma unroll
        for (int j = 0; j < 4; j++)
#pragma unroll
            for (int q = 0; q < 4; q++) { acc1[i][j][q] = 0.f; acc2[i][j][q] = 0.f; }

    for (int kh = 0; kh < 2; kh++) {
        __syncthreads();
#pragma unroll
        for (int t = 0; t < 2; t++) {
            int i = tid + t * 512;
            int r = i >> 3, oo = i & 7;
            uint32_t soff = SW128((uint32_t)(r * 128 + oo * 16));
            size_t elem = (size_t)(row0 + r) * 128 + kh * 64 + oo * 8;
            size_t bidx = ((size_t)r * 128 + kh * 64 + oo * 8) >> 3;
            bool av = (row0 + r) < n;
            uint4 va = av ? reinterpret_cast<const uint4*>(Ahi)[elem >> 3] : zero4;
            uint4 vb = av ? reinterpret_cast<const uint4*>(Alo)[elem >> 3] : zero4;
            *reinterpret_cast<uint4*>(smem + (sAhi - sb)  + soff) = va;
            *reinterpret_cast<uint4*>(smem + (sAlo - sb)  + soff) = vb;
            *reinterpret_cast<uint4*>(smem + (sB1hi - sb) + soff) = reinterpret_cast<const uint4*>(B1hi)[bidx];
            *reinterpret_cast<uint4*>(smem + (sB1lo - sb) + soff) = reinterpret_cast<const uint4*>(B1lo)[bidx];
            *reinterpret_cast<uint4*>(smem + (sB2hi - sb) + soff) = reinterpret_cast<const uint4*>(B2hi)[bidx];
            *reinterpret_cast<uint4*>(smem + (sB2lo - sb) + soff) = reinterpret_cast<const uint4*>(B2lo)[bidx];
        }
        __syncthreads();

#pragma unroll
        for (int kk = 0; kk < 4; kk++) {
            int lr = lane & 15;
            int kin = kk * 16 + ((lane >> 4) << 3);
            uint32_t ahi[2][4], alo[2][4];
#pragma unroll
            for (int mf = 0; mf < 2; mf++) {
                uint32_t off = SW128((uint32_t)((wm * 32 + mf * 16 + lr) * 128 + kin * 2));
                LDSM4(ahi[mf][0], ahi[mf][1], ahi[mf][2], ahi[mf][3], sAhi + off);
                LDSM4(alo[mf][0], alo[mf][1], alo[mf][2], alo[mf][3], sAlo + off);
            }
            uint32_t boff[2];
#pragma unroll
            for (int nf = 0; nf < 2; nf++)
                boff[nf] = SW128((uint32_t)((wn * 32 + nf * 16 + lr) * 128 + kin * 2));

#pragma unroll
            for (int g = 0; g < 2; g++) {
                uint32_t hbase = g ? sB2hi : sB1hi;
                uint32_t lbase = g ? sB2lo : sB1lo;
                uint32_t bxh[2][4], bxl[2][4];
#pragma unroll
                for (int nf = 0; nf < 2; nf++) {
                    LDSM4(bxh[nf][0], bxh[nf][1], bxh[nf][2], bxh[nf][3], hbase + boff[nf]);
                    LDSM4(bxl[nf][0], bxl[nf][1], bxl[nf][2], bxl[nf][3], lbase + boff[nf]);
                }
#pragma unroll
                for (int mf = 0; mf < 2; mf++) {
#pragma unroll
                    for (int ns = 0; ns < 4; ns++) {
                        int gg = ns >> 1, od = ns & 1;
                        uint32_t bh[2] = { bxh[gg][od], bxh[gg][od + 2] };
                        uint32_t bl[2] = { bxl[gg][od], bxl[gg][od + 2] };
                        float* a = g ? acc2[mf][ns] : acc1[mf][ns];
                        mma16816(a, ahi[mf], bh);
                        mma16816(a, ahi[mf], bl);
                        mma16816(a, alo[mf], bh);
                    }
                }
            }
        }
    }

    int qrow = lane >> 2, qcol = (lane & 3) * 2;
#pragma unroll
    for (int mf = 0; mf < 2; mf++) {
#pragma unroll
        for (int ns = 0; ns < 4; ns++) {
            int r0 = row0 + wm * 32 + mf * 16 + qrow;
            int c0 = wn * 32 + ns * 8 + qcol;
            if (r0 < n) {
                __half2 h1 = __floats2half2_rn(acc1[mf][ns][0], acc1[mf][ns][1]);
                __half2 h2 = __floats2half2_rn(acc2[mf][ns][0], acc2[mf][ns][1]);
                *reinterpret_cast<uint32_t*>(&C1[(size_t)r0 * 128 + c0]) = *(uint32_t*)&h1;
                *reinterpret_cast<uint32_t*>(&C2[(size_t)r0 * 128 + c0]) = *(uint32_t*)&h2;
            }
            if (r0 + 8 < n) {
                __half2 h1 = __floats2half2_rn(acc1[mf][ns][2], acc1[mf][ns][3]);
                __half2 h2 = __floats2half2_rn(acc2[mf][ns][2], acc2[mf][ns][3]);
                *reinterpret_cast<uint32_t*>(&C1[(size_t)(r0 + 8) * 128 + c0]) = *(uint32_t*)&h1;
                *reinterpret_cast<uint32_t*>(&C2[(size_t)(r0 + 8) * 128 + c0]) = *(uint32_t*)&h2;
            }
        }
    }
}

// ---------------- warp helpers ----------------
__device__ __forceinline__ float warp_sum(float v) {
#pragma unroll
    for (int o = 16; o; o >>= 1) v += __shfl_xor_sync(0xffffffffu, v, o);
    return v;
}

__device__ __forceinline__ float lrelu(float x) { return x >= 0.f ? x : 0.2f * x; }
__device__ __forceinline__ float elu(float x)  { return x > 0.f ? x : expm1f(x); }

// ---------------- fused GAT aggregation ----------------
__global__ void k_edgeagg(const __half* __restrict__ h,
                          const float* __restrict__ xprev_f,
                          __nv_bfloat16* __restrict__ xhi,
                          __nv_bfloat16* __restrict__ xlo, int n)
{
    __shared__ int   sidx[8][32];
    __shared__ float4 swt[8][32];

    int w = threadIdx.x >> 5;
    int gw = (blockIdx.x * blockDim.x + threadIdx.x) >> 5;
    int lane = threadIdx.x & 31;
    if (gw >= n) return;

    int base = g_rowptr[gw];
    int deg  = g_rowptr[gw + 1] - base;
    float4 ad = g_adst[gw];
    float4 acc = make_float4(0.f, 0.f, 0.f, 0.f);
    int hsel = lane >> 3;

    if (deg <= 32) {
        int myidx = 0;
        float p0 = 0.f, p1 = 0.f, p2 = 0.f, p3 = 0.f;
        if (lane < deg) {
            myidx = g_col[base + lane];
            float4 as = g_asrc[myidx];
            p0 = expf(fminf(lrelu(as.x + ad.x), 75.f));
            p1 = expf(fminf(lrelu(as.y + ad.y), 75.f));
            p2 = expf(fminf(lrelu(as.z + ad.z), 75.f));
            p3 = expf(fminf(lrelu(as.w + ad.w), 75.f));
        }
        float i0 = 1.f / (warp_sum(p0) + 1e-10f);
        float i1 = 1.f / (warp_sum(p1) + 1e-10f);
        float i2 = 1.f / (warp_sum(p2) + 1e-10f);
        float i3 = 1.f / (warp_sum(p3) + 1e-10f);
        sidx[w][lane] = myidx;
        swt[w][lane] = make_float4(p0 * i0, p1 * i1, p2 * i2, p3 * i3);
        __syncwarp();
#pragma unroll 4
        for (int j = 0; j < deg; j++) {
            int s = sidx[w][j];
            float wj = reinterpret_cast<const float*>(&swt[w][j])[hsel];
            uint2 raw = *reinterpret_cast<const uint2*>(&h[(size_t)s * 128 + 4 * lane]);
            float2 f01 = __half22float2(*reinterpret_cast<const __half2*>(&raw.x));
            float2 f23 = __half22float2(*reinterpret_cast<const __half2*>(&raw.y));
            acc.x += f01.x * wj;
            acc.y += f01.y * wj;
            acc.z += f23.x * wj;
            acc.w += f23.y * wj;
        }
    } else {
        float s0 = 0.f, s1 = 0.f, s2 = 0.f, s3 = 0.f;
        for (int i = lane; i < deg; i += 32) {
            int s = g_col[base + i];
            float4 as = g_asrc[s];
            float p0 = expf(fminf(lrelu(as.x + ad.x), 75.f));
            float p1 = expf(fminf(lrelu(as.y + ad.y), 75.f));
            float p2 = expf(fminf(lrelu(as.z + ad.z), 75.f));
            float p3 = expf(fminf(lrelu(as.w + ad.w), 75.f));
            g_ew[base + i] = make_float4(p0, p1, p2, p3);
            s0 += p0; s1 += p1; s2 += p2; s3 += p3;
        }
        s0 = warp_sum(s0); s1 = warp_sum(s1); s2 = warp_sum(s2); s3 = warp_sum(s3);
        float i0 = 1.f / (s0 + 1e-10f);
        float i1 = 1.f / (s1 + 1e-10f);
        float i2 = 1.f / (s2 + 1e-10f);
        float i3 = 1.f / (s3 + 1e-10f);

        for (int bi = 0; bi < deg; bi += 32) {
            int cnt = min(32, deg - bi);
            if (lane < cnt) {
                sidx[w][lane] = g_col[base + bi + lane];
                float4 p = g_ew[base + bi + lane];
                swt[w][lane] = make_float4(p.x * i0, p.y * i1, p.z * i2, p.w * i3);
            }
            __syncwarp();
#pragma unroll 4
            for (int j = 0; j < cnt; j++) {
                int s = sidx[w][j];
                float wj = reinterpret_cast<const float*>(&swt[w][j])[hsel];
                uint2 raw = *reinterpret_cast<const uint2*>(&h[(size_t)s * 128 + 4 * lane]);
                float2 f01 = __half22float2(*reinterpret_cast<const __half2*>(&raw.x));
                float2 f23 = __half22float2(*reinterpret_cast<const __half2*>(&raw.y));
                acc.x += f01.x * wj;
                acc.y += f01.y * wj;
                acc.z += f23.x * wj;
                acc.w += f23.y * wj;
            }
            __syncwarp();
        }
    }

    size_t o = (size_t)gw * 128 + 4 * lane;
    float4 xp;
    if (xprev_f) {
        xp = *reinterpret_cast<const float4*>(&xprev_f[o]);
    } else {
        uint2 rh = *reinterpret_cast<const uint2*>(&xhi[o]);
        uint2 rl = *reinterpret_cast<const uint2*>(&xlo[o]);
        __nv_bfloat162 h0 = *reinterpret_cast<const __nv_bfloat162*>(&rh.x);
        __nv_bfloat162 h1 = *reinterpret_cast<const __nv_bfloat162*>(&rh.y);
        __nv_bfloat162 l0 = *reinterpret_cast<const __nv_bfloat162*>(&rl.x);
        __nv_bfloat162 l1 = *reinterpret_cast<const __nv_bfloat162*>(&rl.y);
        xp = make_float4(__bfloat162float(h0.x) + __bfloat162float(l0.x),
                         __bfloat162float(h0.y) + __bfloat162float(l0.y),
                         __bfloat162float(h1.x) + __bfloat162float(l1.x),
                         __bfloat162float(h1.y) + __bfloat162float(l1.y));
    }
    float4 v = make_float4(elu(acc.x) + xp.x, elu(acc.y) + xp.y,
                           elu(acc.z) + xp.z, elu(acc.w) + xp.w);
    {
        __nv_bfloat162 h0 = __floats2bfloat162_rn(v.x, v.y);
        __nv_bfloat162 h1 = __floats2bfloat162_rn(v.z, v.w);
        __nv_bfloat162 l0 = __floats2bfloat162_rn(v.x - __bfloat162float(h0.x), v.y - __bfloat162float(h0.y));
        __nv_bfloat162 l1 = __floats2bfloat162_rn(v.z - __bfloat162float(h1.x), v.w - __bfloat162float(h1.y));
        uint2 ph = make_uint2(*(uint32_t*)&h0, *(uint32_t*)&h1);
        uint2 pl = make_uint2(*(uint32_t*)&l0, *(uint32_t*)&l1);
        *reinterpret_cast<uint2*>(&xhi[o]) = ph;
        *reinterpret_cast<uint2*>(&xlo[o]) = pl;
    }
}

// ---------------- pair epilogue ----------------
__global__ void k_pairs(const int* __restrict__ lsrc, const int* __restrict__ ldst,
                        const float* __restrict__ b1, const float* __restrict__ w2,
                        const float* __restrict__ b2, float* __restrict__ out, int p)
{
    int gw = (blockIdx.x * blockDim.x + threadIdx.x) >> 5;
    int lane = threadIdx.x & 31;
    if (gw >= p) return;
    int k = 4 * lane;
    uint2 ru = *reinterpret_cast<const uint2*>(&g_u[(size_t)lsrc[gw] * 128 + k]);
    uint2 rv = *reinterpret_cast<const uint2*>(&g_v[(size_t)ldst[gw] * 128 + k]);
    float2 u01 = __half22float2(*reinterpret_cast<const __half2*>(&ru.x));
    float2 u23 = __half22float2(*reinterpret_cast<const __half2*>(&ru.y));
    float2 v01 = __half22float2(*reinterpret_cast<const __half2*>(&rv.x));
    float2 v23 = __half22float2(*reinterpret_cast<const __half2*>(&rv.y));
    float4 b = *reinterpret_cast<const float4*>(&b1[k]);
    float4 w = *reinterpret_cast<const float4*>(&w2[k]);
    float t = fmaxf(u01.x + v01.x + b.x, 0.f) * w.x
            + fmaxf(u01.y + v01.y + b.y, 0.f) * w.y
            + fmaxf(u23.x + v23.x + b.z, 0.f) * w.z
            + fmaxf(u23.y + v23.y + b.w, 0.f) * w.w;
    t = warp_sum(t);
    if (lane == 0) out[gw] = t + b2[0];
}

// ---------------- driver ----------------
extern "C" void kernel_launch(void* const* d_in, const int* in_sizes, int n_in,
                              void* d_out, int out_size)
{
    const float* embed  = (const float*)d_in[0];
    const float* W1     = (const float*)d_in[1];
    const float* a_src1 = (const float*)d_in[2];
    const float* a_dst1 = (const float*)d_in[3];
    const float* W2     = (const float*)d_in[4];
    const float* a_src2 = (const float*)d_in[5];
    const float* a_dst2 = (const float*)d_in[6];
    const float* lp_w1  = (const float*)d_in[7];
    const float* lp_b1  = (const float*)d_in[8];
    const float* lp_w2  = (const float*)d_in[9];
    const float* lp_b2  = (const float*)d_in[10];
    const int*   eidx   = (const int*)d_in[11];
    const int*   lsrc   = (const int*)d_in[12];
    const int*   ldst   = (const int*)d_in[13];
    float* out = (float*)d_out;

    const int N = in_sizes[0] / DDIM;
    const int E = in_sizes[11] / 2;
    const int P = in_sizes[12];
    const int* esrc = eidx;
    const int* edst = eidx + E;

    __half* hbuf; cudaGetSymbolAddress((void**)&hbuf, g_h);
    __half* ub;   cudaGetSymbolAddress((void**)&ub,   g_u);
    __half* vb;   cudaGetSymbolAddress((void**)&vb,   g_v);
    __nv_bfloat16* ahi; cudaGetSymbolAddress((void**)&ahi, g_ahi);
    __nv_bfloat16* alo; cudaGetSymbolAddress((void**)&alo, g_alo);
    __nv_bfloat16* wthi; cudaGetSymbolAddress((void**)&wthi, g_wthi);
    __nv_bfloat16* wtlo; cudaGetSymbolAddress((void**)&wtlo, g_wtlo);

    cudaFuncSetAttribute(k_gemm_mma,  cudaFuncAttributeMaxDynamicSharedMemorySize, GEMM_SMEM);
    cudaFuncSetAttribute(k_gemm_mma2, cudaFuncAttributeMaxDynamicSharedMemorySize, GEMM2_SMEM);

    const int T = 256;
    int nbN  = (N + T - 1) / T;
    int nbE  = (E + T - 1) / T;
    int nbS  = (N + 1023) / 1024;
    int nbW  = (N * 32 + T - 1) / T;
    int nbPW = (P * 32 + T - 1) / T;
    int nbG  = (N + 127) / 128;
    const int WSZ = DDIM * DDIM;

    k_setup<<<nbN, T>>>(W1, W2, lp_w1, wthi, wtlo, N);      // 0
    k_hist<<<nbE, T>>>(edst, E);                            // 1
    k_scan1<<<nbS, 1024>>>(N);                              // 2
    k_gemm_mma<<<nbG, 512, GEMM_SMEM>>>(embed, nullptr, nullptr,   // 3 (profiled)
                                        wthi + 0 * WSZ, wtlo + 0 * WSZ, hbuf,
                                        a_src1, a_dst1, N);
    k_scan2<<<1, 128>>>(nbS);                               // 4
    k_scan3<<<nbS, 1024>>>(N, E);                           // 5
    k_scatter<<<nbE, T>>>(esrc, edst, E);                   // 6

    k_edgeagg<<<nbW, T>>>(hbuf, embed, ahi, alo, N);        // 7

    k_gemm_mma<<<nbG, 512, GEMM_SMEM>>>(nullptr, ahi, alo,  // 8
                                        wthi + 1 * WSZ, wtlo + 1 * WSZ, hbuf,
                                        a_src2, a_dst2, N);
    k_edgeagg<<<nbW, T>>>(hbuf, nullptr, ahi, alo, N);      // 9

    k_gemm_mma2<<<nbG, 512, GEMM2_SMEM>>>(ahi, alo,         // 10
                                          wthi + 2 * WSZ, wtlo + 2 * WSZ,
                                          wthi + 3 * WSZ, wtlo + 3 * WSZ,
                                          ub, vb, N);
    k_pairs<<<nbPW, T>>>(lsrc, ldst, lp_b1, lp_w2, lp_b2, out, P);  // 11
}

// round 13
// speedup vs baseline: 1.5696x; 1.5696x over previous
#include <cuda_runtime.h>
#include <cuda_bf16.h>
#include <cuda_fp16.h>
#include <math.h>
#include <stdint.h>

#define NMAX 100000
#define EMAX 1600000
#define DDIM 128

// ---------------- scratch ----------------
__device__ __half g_h [NMAX * DDIM];     // transformed features (GEMM out)
__device__ __half g_x [NMAX * DDIM];     // current node state (residual chain)
__device__ __half g_u [NMAX * DDIM];
__device__ __half g_v [NMAX * DDIM];
__device__ __half g_wt[4 * DDIM * DDIM]; // K-major fp16 weights
__device__ float4 g_asrc[NMAX];
__device__ float4 g_adst[NMAX];
__device__ float4 g_ew  [EMAX];
__device__ int g_deg   [NMAX];
__device__ int g_rowptr[NMAX + 1];
__device__ int g_cursor[NMAX];
__device__ int g_col   [EMAX];
__device__ int g_bsums [1024];

__device__ __forceinline__ uint32_t smem_to_u32(const void* p) {
    uint32_t a;
    asm("{ .reg .u64 t; cvta.to.shared.u64 t, %1; cvt.u32.u64 %0, t; }" : "=r"(a) : "l"(p));
    return a;
}
#define SW128(off) ((off) ^ (((off) >> 3) & 0x70))

#define LDSM4(r0, r1, r2, r3, addr) \
    asm volatile("ldmatrix.sync.aligned.m8n8.x4.shared.b16 {%0,%1,%2,%3}, [%4];" \
        : "=r"(r0), "=r"(r1), "=r"(r2), "=r"(r3) : "r"(addr))

__device__ __forceinline__ void mma16816(float* d, const uint32_t* a, const uint32_t* b) {
    asm volatile(
        "mma.sync.aligned.m16n8k16.row.col.f32.f16.f16.f32 "
        "{%0,%1,%2,%3},{%4,%5,%6,%7},{%8,%9},{%0,%1,%2,%3};"
        : "+f"(d[0]), "+f"(d[1]), "+f"(d[2]), "+f"(d[3])
        : "r"(a[0]), "r"(a[1]), "r"(a[2]), "r"(a[3]), "r"(b[0]), "r"(b[1]));
}

// ---------------- setup: zero degrees + 4 weight transposes to fp16 --------
__device__ __forceinline__ void wconv_one(const float* __restrict__ W,
                                          __half* __restrict__ wt, int i) {
    int nn = i >> 6;
    int kp = (i & 63) * 2;
    float x0 = W[(size_t)kp * 128 + nn];
    float x1 = W[(size_t)(kp + 1) * 128 + nn];
    reinterpret_cast<__half2*>(wt)[i] = __floats2half2_rn(x0, x1);
}

__global__ void k_setup(const float* __restrict__ W1, const float* __restrict__ W2,
                        const float* __restrict__ lpw1,
                        __half* __restrict__ wt, int n) {
    const int WSZ = DDIM * DDIM;
    int i = blockIdx.x * blockDim.x + threadIdx.x;
    if (i < n) g_deg[i] = 0;
    if (i < 8192)       wconv_one(W1,               wt + 0 * WSZ, i);
    else if (i < 16384) wconv_one(W2,               wt + 1 * WSZ, i - 8192);
    else if (i < 24576) wconv_one(lpw1,             wt + 2 * WSZ, i - 16384);
    else if (i < 32768) wconv_one(lpw1 + 128 * 128, wt + 3 * WSZ, i - 24576);
}

// ---------------- CSR build ----------------
__global__ void k_hist(const int* __restrict__ dst, int e) {
    int i = blockIdx.x * blockDim.x + threadIdx.x;
    if (i < e) atomicAdd(&g_deg[dst[i]], 1);
}
__global__ void k_scan1(int n) {
    __shared__ int ws[32];
    int tid = threadIdx.x;
    int lane = tid & 31, w = tid >> 5;
    int i = blockIdx.x * 1024 + tid;
    int v = (i < n) ? g_deg[i] : 0;
    int x = v;
#pragma unroll
    for (int o = 1; o < 32; o <<= 1) {
        int t = __shfl_up_sync(0xffffffffu, x, o);
        if (lane >= o) x += t;
    }
    if (lane == 31) ws[w] = x;
    __syncthreads();
    if (w == 0) {
        int t = ws[lane];
        int s = t;
#pragma unroll
        for (int o = 1; o < 32; o <<= 1) {
            int q = __shfl_up_sync(0xffffffffu, s, o);
            if (lane >= o) s += q;
        }
        ws[lane] = s - t;
    }
    __syncthreads();
    int incl = x + ws[w];
    if (i < n) g_rowptr[i] = incl - v;
    if (tid == 1023) g_bsums[blockIdx.x] = incl;
}
__global__ void k_scan2(int nb) {
    __shared__ int wsum[4];
    int tid = threadIdx.x;
    int lane = tid & 31, w = tid >> 5;
    int v = (tid < nb) ? g_bsums[tid] : 0;
    int x = v;
#pragma unroll
    for (int o = 1; o < 32; o <<= 1) {
        int t = __shfl_up_sync(0xffffffffu, x, o);
        if (lane >= o) x += t;
    }
    if (lane == 31) wsum[w] = x;
    __syncthreads();
    int add = 0;
#pragma unroll
    for (int j = 0; j < 4; j++) add += (j < w) ? wsum[j] : 0;
    if (tid < nb) g_bsums[tid] = x - v + add;
}
__global__ void k_scan3(int n, int e) {
    int i = blockIdx.x * 1024 + threadIdx.x;
    if (i < n) {
        int v = g_rowptr[i] + g_bsums[blockIdx.x];
        g_rowptr[i] = v;
        g_cursor[i] = v;
    }
    if (i == 0) g_rowptr[n] = e;
}
__global__ void k_scatter(const int* __restrict__ src, const int* __restrict__ dst, int e) {
    int i = blockIdx.x * blockDim.x + threadIdx.x;
    if (i < e) {
        int d = dst[i];
        int slot = atomicAdd(&g_cursor[d], 1);
        g_col[slot] = src[i];
    }
}

// ---------------- fp16 HMMA GEMM, block 128x128, full-K smem (64KB) --------
#define GEMM_SMEM 65536

__global__ void __launch_bounds__(512, 1) k_gemm_mma(
    const float* __restrict__ Af,          // fp32 A (layer 1) or null
    const __half* __restrict__ Ax,         // fp16 A otherwise
    const __half* __restrict__ B,          // fp16 Wt[n][k]
    __half* __restrict__ C,
    const float* __restrict__ a_src, const float* __restrict__ a_dst, int n)
{
    extern __shared__ char smem[];
    __shared__ float sAl[128][4];
    __shared__ float sDl[128][4];
    uint32_t sb = smem_to_u32(smem);
    const uint32_t sA = sb;
    const uint32_t sB = sb + 32768;

    int tid = threadIdx.x;
    int wid = tid >> 5, lane = tid & 31;
    int wm = wid & 3, wn = wid >> 2;
    int row0 = blockIdx.x * 128;

    if (tid < 128) {
        *reinterpret_cast<float4*>(&sAl[tid][0]) = make_float4(0.f, 0.f, 0.f, 0.f);
        *reinterpret_cast<float4*>(&sDl[tid][0]) = make_float4(0.f, 0.f, 0.f, 0.f);
    }

    float acc[2][4][4];
#pragma unroll
    for (int i = 0; i < 2; i++)
#pragma unroll
        for (int j = 0; j < 4; j++)
#pragma unroll
            for (int q = 0; q < 4; q++) acc[i][j][q] = 0.f;

    const uint4 zero4 = make_uint4(0, 0, 0, 0);

    // A+B load: each 2048 uint4, 512 threads -> 4 iters each
#pragma unroll
    for (int t = 0; t < 4; t++) {
        int i = tid + t * 512;
        int r = i >> 4;
        int o = i & 15;
        int kh = o >> 3, oo = o & 7;
        uint32_t soff = (uint32_t)(kh * 16384) + SW128((uint32_t)(r * 128 + oo * 16));
        size_t elem = (size_t)(row0 + r) * 128 + kh * 64 + oo * 8;
        size_t bidx = ((size_t)r * 128 + kh * 64 + oo * 8) >> 3;
        bool av = (row0 + r) < n;
        uint4 va;
        if (Af) {
            float4 f0 = make_float4(0.f, 0.f, 0.f, 0.f), f1 = f0;
            if (av) {
                f0 = *reinterpret_cast<const float4*>(&Af[elem]);
                f1 = *reinterpret_cast<const float4*>(&Af[elem + 4]);
            }
            __half2 h0 = __floats2half2_rn(f0.x, f0.y);
            __half2 h1 = __floats2half2_rn(f0.z, f0.w);
            __half2 h2 = __floats2half2_rn(f1.x, f1.y);
            __half2 h3 = __floats2half2_rn(f1.z, f1.w);
            va = make_uint4(*(uint32_t*)&h0, *(uint32_t*)&h1, *(uint32_t*)&h2, *(uint32_t*)&h3);
        } else {
            va = av ? reinterpret_cast<const uint4*>(Ax)[elem >> 3] : zero4;
        }
        *reinterpret_cast<uint4*>(smem + (sA - sb) + soff) = va;
        *reinterpret_cast<uint4*>(smem + (sB - sb) + soff) = reinterpret_cast<const uint4*>(B)[bidx];
    }
    __syncthreads();

#pragma unroll
    for (int kh = 0; kh < 2; kh++) {
        uint32_t hoff = (uint32_t)(kh * 16384);
#pragma unroll
        for (int kk = 0; kk < 4; kk++) {
            int lr = lane & 15;
            int kin = kk * 16 + ((lane >> 4) << 3);
            uint32_t af[2][4], bf[2][4];
#pragma unroll
            for (int mf = 0; mf < 2; mf++) {
                uint32_t off = hoff + SW128((uint32_t)((wm * 32 + mf * 16 + lr) * 128 + kin * 2));
                LDSM4(af[mf][0], af[mf][1], af[mf][2], af[mf][3], sA + off);
            }
#pragma unroll
            for (int nf = 0; nf < 2; nf++) {
                uint32_t off = hoff + SW128((uint32_t)((wn * 32 + nf * 16 + lr) * 128 + kin * 2));
                LDSM4(bf[nf][0], bf[nf][1], bf[nf][2], bf[nf][3], sB + off);
            }
#pragma unroll
            for (int mf = 0; mf < 2; mf++) {
#pragma unroll
                for (int ns = 0; ns < 4; ns++) {
                    int g = ns >> 1, od = ns & 1;
                    uint32_t bb[2] = { bf[g][od], bf[g][od + 2] };
                    mma16816(acc[mf][ns], af[mf], bb);
                }
            }
        }
    }

    int qrow = lane >> 2, qcol = (lane & 3) * 2;

    // fused alpha partial dots (fp32)
    {
        float2 s2[4], d2[4];
#pragma unroll
        for (int ns = 0; ns < 4; ns++) {
            int c = wn * 32 + ns * 8 + qcol;
            s2[ns] = *reinterpret_cast<const float2*>(&a_src[c]);
            d2[ns] = *reinterpret_cast<const float2*>(&a_dst[c]);
        }
#pragma unroll
        for (int mf = 0; mf < 2; mf++) {
            int rl = wm * 32 + mf * 16 + qrow;
            float pa0 = 0.f, pd0 = 0.f, pa1 = 0.f, pd1 = 0.f;
#pragma unroll
            for (int ns = 0; ns < 4; ns++) {
                pa0 += acc[mf][ns][0] * s2[ns].x + acc[mf][ns][1] * s2[ns].y;
                pd0 += acc[mf][ns][0] * d2[ns].x + acc[mf][ns][1] * d2[ns].y;
                pa1 += acc[mf][ns][2] * s2[ns].x + acc[mf][ns][3] * s2[ns].y;
                pd1 += acc[mf][ns][2] * d2[ns].x + acc[mf][ns][3] * d2[ns].y;
            }
            atomicAdd(&sAl[rl][wn], pa0);     atomicAdd(&sDl[rl][wn], pd0);
            atomicAdd(&sAl[rl + 8][wn], pa1); atomicAdd(&sDl[rl + 8][wn], pd1);
        }
    }

    // h store fp16
#pragma unroll
    for (int mf = 0; mf < 2; mf++) {
#pragma unroll
        for (int ns = 0; ns < 4; ns++) {
            int r0 = row0 + wm * 32 + mf * 16 + qrow;
            int c0 = wn * 32 + ns * 8 + qcol;
            if (r0 < n) {
                __half2 hv = __floats2half2_rn(acc[mf][ns][0], acc[mf][ns][1]);
                *reinterpret_cast<uint32_t*>(&C[(size_t)r0 * 128 + c0]) = *(uint32_t*)&hv;
            }
            if (r0 + 8 < n) {
                __half2 hv = __floats2half2_rn(acc[mf][ns][2], acc[mf][ns][3]);
                *reinterpret_cast<uint32_t*>(&C[(size_t)(r0 + 8) * 128 + c0]) = *(uint32_t*)&hv;
            }
        }
    }

    __syncthreads();
    if (tid < 128 && row0 + tid < n) {
        g_asrc[row0 + tid] = *reinterpret_cast<float4*>(&sAl[tid][0]);
        g_adst[row0 + tid] = *reinterpret_cast<float4*>(&sDl[tid][0]);
    }
}

// ---------------- dual-B fp16 GEMM (A loaded once, both acc live) ----------
#define GEMM2_SMEM 98304

__global__ void __launch_bounds__(512, 1) k_gemm_mma2(
    const __half* __restrict__ Ax,
    const __half* __restrict__ B1, const __half* __restrict__ B2,
    __half* __restrict__ C1, __half* __restrict__ C2, int n)
{
    extern __shared__ char smem[];
    uint32_t sb = smem_to_u32(smem);
    const uint32_t sA  = sb;
    const uint32_t sB1 = sb + 32768;
    const uint32_t sB2 = sb + 65536;

    int tid = threadIdx.x;
    int wid = tid >> 5, lane = tid & 31;
    int wm = wid & 3, wn = wid >> 2;
    int row0 = blockIdx.x * 128;

    const uint4 zero4 = make_uint4(0, 0, 0, 0);

    float acc1[2][4][4], acc2[2][4][4];
#pragma unroll
    for (int i = 0; i < 2; i++)
#pragma unroll
        for (int j = 0; j < 4; j++)
#pragma unroll
            for (int q = 0; q < 4; q++) { acc1[i][j][q] = 0.f; acc2[i][j][q] = 0.f; }

#pragma unroll
    for (int t = 0; t < 4; t++) {
        int i = tid + t * 512;
        int r = i >> 4;
        int o = i & 15;
        int kh = o >> 3, oo = o & 7;
        uint32_t soff = (uint32_t)(kh * 16384) + SW128((uint32_t)(r * 128 + oo * 16));
        size_t elem = (size_t)(row0 + r) * 128 + kh * 64 + oo * 8;
        size_t bidx = ((size_t)r * 128 + kh * 64 + oo * 8) >> 3;
        bool av = (row0 + r) < n;
        uint4 va = av ? reinterpret_cast<const uint4*>(Ax)[elem >> 3] : zero4;
        *reinterpret_cast<uint4*>(smem + (sA - sb)  + soff) = va;
        *reinterpret_cast<uint4*>(smem + (sB1 - sb) + soff) = reinterpret_cast<const uint4*>(B1)[bidx];
        *reinterpret_cast<uint4*>(smem + (sB2 - sb) + soff) = reinterpret_cast<const uint4*>(B2)[bidx];
    }
    __syncthreads();

#pragma unroll
    for (int kh = 0; kh < 2; kh++) {
        uint32_t hoff = (uint32_t)(kh * 16384);
#pragma unroll
        for (int kk = 0; kk < 4; kk++) {
            int lr = lane & 15;
            int kin = kk * 16 + ((lane >> 4) << 3);
            uint32_t af[2][4], b1f[2][4], b2f[2][4];
#pragma unroll
            for (int mf = 0; mf < 2; mf++) {
                uint32_t off = hoff + SW128((uint32_t)((wm * 32 + mf * 16 + lr) * 128 + kin * 2));
                LDSM4(af[mf][0], af[mf][1], af[mf][2], af[mf][3], sA + off);
            }
#pragma unroll
            for (int nf = 0; nf < 2; nf++) {
                uint32_t off = hoff + SW128((uint32_t)((wn * 32 + nf * 16 + lr) * 128 + kin * 2));
                LDSM4(b1f[nf][0], b1f[nf][1], b1f[nf][2], b1f[nf][3], sB1 + off);
                LDSM4(b2f[nf][0], b2f[nf][1], b2f[nf][2], b2f[nf][3], sB2 + off);
            }
#pragma unroll
            for (int mf = 0; mf < 2; mf++) {
#pragma unroll
                for (int ns = 0; ns < 4; ns++) {
                    int g = ns >> 1, od = ns & 1;
                    uint32_t bb1[2] = { b1f[g][od], b1f[g][od + 2] };
                    uint32_t bb2[2] = { b2f[g][od], b2f[g][od + 2] };
                    mma16816(acc1[mf][ns], af[mf], bb1);
                    mma16816(acc2[mf][ns], af[mf], bb2);
                }
            }
        }
    }

    int qrow = lane >> 2, qcol = (lane & 3) * 2;
#pragma unroll
    for (int mf = 0; mf < 2; mf++) {
#pragma unroll
        for (int ns = 0; ns < 4; ns++) {
            int r0 = row0 + wm * 32 + mf * 16 + qrow;
            int c0 = wn * 32 + ns * 8 + qcol;
            if (r0 < n) {
                __half2 h1 = __floats2half2_rn(acc1[mf][ns][0], acc1[mf][ns][1]);
                __half2 h2 = __floats2half2_rn(acc2[mf][ns][0], acc2[mf][ns][1]);
                *reinterpret_cast<uint32_t*>(&C1[(size_t)r0 * 128 + c0]) = *(uint32_t*)&h1;
                *reinterpret_cast<uint32_t*>(&C2[(size_t)r0 * 128 + c0]) = *(uint32_t*)&h2;
            }
            if (r0 + 8 < n) {
                __half2 h1 = __floats2half2_rn(acc1[mf][ns][2], acc1[mf][ns][3]);
                __half2 h2 = __floats2half2_rn(acc2[mf][ns][2], acc2[mf][ns][3]);
                *reinterpret_cast<uint32_t*>(&C1[(size_t)(r0 + 8) * 128 + c0]) = *(uint32_t*)&h1;
                *reinterpret_cast<uint32_t*>(&C2[(size_t)(r0 + 8) * 128 + c0]) = *(uint32_t*)&h2;
            }
        }
    }
}

// ---------------- warp helpers ----------------
__device__ __forceinline__ float warp_sum(float v) {
#pragma unroll
    for (int o = 16; o; o >>= 1) v += __shfl_xor_sync(0xffffffffu, v, o);
    return v;
}

__device__ __forceinline__ float lrelu(float x) { return x >= 0.f ? x : 0.2f * x; }
__device__ __forceinline__ float elu(float x)  { return x > 0.f ? x : expm1f(x); }

// ---------------- fused GAT aggregation ----------------
// xprev: fp32 (layer 1) or fp16 in-place from x. Output -> x (fp16).
__global__ void k_edgeagg(const __half* __restrict__ h,
                          const float* __restrict__ xprev_f,
                          __half* __restrict__ x, int n)
{
    __shared__ int   sidx[8][32];
    __shared__ float4 swt[8][32];

    int w = threadIdx.x >> 5;
    int gw = (blockIdx.x * blockDim.x + threadIdx.x) >> 5;
    int lane = threadIdx.x & 31;
    if (gw >= n) return;

    int base = g_rowptr[gw];
    int deg  = g_rowptr[gw + 1] - base;
    float4 ad = g_adst[gw];
    float4 acc = make_float4(0.f, 0.f, 0.f, 0.f);
    int hsel = lane >> 3;

    if (deg <= 32) {
        int myidx = 0;
        float p0 = 0.f, p1 = 0.f, p2 = 0.f, p3 = 0.f;
        if (lane < deg) {
            myidx = g_col[base + lane];
            float4 as = g_asrc[myidx];
            p0 = expf(fminf(lrelu(as.x + ad.x), 75.f));
            p1 = expf(fminf(lrelu(as.y + ad.y), 75.f));
            p2 = expf(fminf(lrelu(as.z + ad.z), 75.f));
            p3 = expf(fminf(lrelu(as.w + ad.w), 75.f));
        }
        float i0 = 1.f / (warp_sum(p0) + 1e-10f);
        float i1 = 1.f / (warp_sum(p1) + 1e-10f);
        float i2 = 1.f / (warp_sum(p2) + 1e-10f);
        float i3 = 1.f / (warp_sum(p3) + 1e-10f);
        sidx[w][lane] = myidx;
        swt[w][lane] = make_float4(p0 * i0, p1 * i1, p2 * i2, p3 * i3);
        __syncwarp();
#pragma unroll 4
        for (int j = 0; j < deg; j++) {
            int s = sidx[w][j];
            float wj = reinterpret_cast<const float*>(&swt[w][j])[hsel];
            uint2 raw = *reinterpret_cast<const uint2*>(&h[(size_t)s * 128 + 4 * lane]);
            float2 f01 = __half22float2(*reinterpret_cast<const __half2*>(&raw.x));
            float2 f23 = __half22float2(*reinterpret_cast<const __half2*>(&raw.y));
            acc.x += f01.x * wj;
            acc.y += f01.y * wj;
            acc.z += f23.x * wj;
            acc.w += f23.y * wj;
        }
    } else {
        float s0 = 0.f, s1 = 0.f, s2 = 0.f, s3 = 0.f;
        for (int i = lane; i < deg; i += 32) {
            int s = g_col[base + i];
            float4 as = g_asrc[s];
            float p0 = expf(fminf(lrelu(as.x + ad.x), 75.f));
            float p1 = expf(fminf(lrelu(as.y + ad.y), 75.f));
            float p2 = expf(fminf(lrelu(as.z + ad.z), 75.f));
            float p3 = expf(fminf(lrelu(as.w + ad.w), 75.f));
            g_ew[base + i] = make_float4(p0, p1, p2, p3);
            s0 += p0; s1 += p1; s2 += p2; s3 += p3;
        }
        s0 = warp_sum(s0); s1 = warp_sum(s1); s2 = warp_sum(s2); s3 = warp_sum(s3);
        float i0 = 1.f / (s0 + 1e-10f);
        float i1 = 1.f / (s1 + 1e-10f);
        float i2 = 1.f / (s2 + 1e-10f);
        float i3 = 1.f / (s3 + 1e-10f);

        for (int bi = 0; bi < deg; bi += 32) {
            int cnt = min(32, deg - bi);
            if (lane < cnt) {
                sidx[w][lane] = g_col[base + bi + lane];
                float4 p = g_ew[base + bi + lane];
                swt[w][lane] = make_float4(p.x * i0, p.y * i1, p.z * i2, p.w * i3);
            }
            __syncwarp();
#pragma unroll 4
            for (int j = 0; j < cnt; j++) {
                int s = sidx[w][j];
                float wj = reinterpret_cast<const float*>(&swt[w][j])[hsel];
                uint2 raw = *reinterpret_cast<const uint2*>(&h[(size_t)s * 128 + 4 * lane]);
                float2 f01 = __half22float2(*reinterpret_cast<const __half2*>(&raw.x));
                float2 f23 = __half22float2(*reinterpret_cast<const __half2*>(&raw.y));
                acc.x += f01.x * wj;
                acc.y += f01.y * wj;
                acc.z += f23.x * wj;
                acc.w += f23.y * wj;
            }
            __syncwarp();
        }
    }

    size_t o = (size_t)gw * 128 + 4 * lane;
    float4 xp;
    if (xprev_f) {
        xp = *reinterpret_cast<const float4*>(&xprev_f[o]);
    } else {
        uint2 rx = *reinterpret_cast<const uint2*>(&x[o]);
        float2 x01 = __half22float2(*reinterpret_cast<const __half2*>(&rx.x));
        float2 x23 = __half22float2(*reinterpret_cast<const __half2*>(&rx.y));
        xp = make_float4(x01.x, x01.y, x23.x, x23.y);
    }
    float4 v = make_float4(elu(acc.x) + xp.x, elu(acc.y) + xp.y,
                           elu(acc.z) + xp.z, elu(acc.w) + xp.w);
    {
        __half2 h0 = __floats2half2_rn(v.x, v.y);
        __half2 h1 = __floats2half2_rn(v.z, v.w);
        uint2 pv = make_uint2(*(uint32_t*)&h0, *(uint32_t*)&h1);
        *reinterpret_cast<uint2*>(&x[o]) = pv;
    }
}

// ---------------- pair epilogue ----------------
__global__ void k_pairs(const int* __restrict__ lsrc, const int* __restrict__ ldst,
                        const float* __restrict__ b1, const float* __restrict__ w2,
                        const float* __restrict__ b2, float* __restrict__ out, int p)
{
    int gw = (blockIdx.x * blockDim.x + threadIdx.x) >> 5;
    int lane = threadIdx.x & 31;
    if (gw >= p) return;
    int k = 4 * lane;
    uint2 ru = *reinterpret_cast<const uint2*>(&g_u[(size_t)lsrc[gw] * 128 + k]);
    uint2 rv = *reinterpret_cast<const uint2*>(&g_v[(size_t)ldst[gw] * 128 + k]);
    float2 u01 = __half22float2(*reinterpret_cast<const __half2*>(&ru.x));
    float2 u23 = __half22float2(*reinterpret_cast<const __half2*>(&ru.y));
    float2 v01 = __half22float2(*reinterpret_cast<const __half2*>(&rv.x));
    float2 v23 = __half22float2(*reinterpret_cast<const __half2*>(&rv.y));
    float4 b = *reinterpret_cast<const float4*>(&b1[k]);
    float4 w = *reinterpret_cast<const float4*>(&w2[k]);
    float t = fmaxf(u01.x + v01.x + b.x, 0.f) * w.x
            + fmaxf(u01.y + v01.y + b.y, 0.f) * w.y
            + fmaxf(u23.x + v23.x + b.z, 0.f) * w.z
            + fmaxf(u23.y + v23.y + b.w, 0.f) * w.w;
    t = warp_sum(t);
    if (lane == 0) out[gw] = t + b2[0];
}

// ---------------- driver ----------------
extern "C" void kernel_launch(void* const* d_in, const int* in_sizes, int n_in,
                              void* d_out, int out_size)
{
    const float* embed  = (const float*)d_in[0];
    const float* W1     = (const float*)d_in[1];
    const float* a_src1 = (const float*)d_in[2];
    const float* a_dst1 = (const float*)d_in[3];
    const float* W2     = (const float*)d_in[4];
    const float* a_src2 = (const float*)d_in[5];
    const float* a_dst2 = (const float*)d_in[6];
    const float* lp_w1  = (const float*)d_in[7];
    const float* lp_b1  = (const float*)d_in[8];
    const float* lp_w2  = (const float*)d_in[9];
    const float* lp_b2  = (const float*)d_in[10];
    const int*   eidx   = (const int*)d_in[11];
    const int*   lsrc   = (const int*)d_in[12];
    const int*   ldst   = (const int*)d_in[13];
    float* out = (float*)d_out;

    const int N = in_sizes[0] / DDIM;
    const int E = in_sizes[11] / 2;
    const int P = in_sizes[12];
    const int* esrc = eidx;
    const int* edst = eidx + E;

    __half* hbuf; cudaGetSymbolAddress((void**)&hbuf, g_h);
    __half* xbuf; cudaGetSymbolAddress((void**)&xbuf, g_x);
    __half* ub;   cudaGetSymbolAddress((void**)&ub,   g_u);
    __half* vb;   cudaGetSymbolAddress((void**)&vb,   g_v);
    __half* wt;   cudaGetSymbolAddress((void**)&wt,   g_wt);

    cudaFuncSetAttribute(k_gemm_mma,  cudaFuncAttributeMaxDynamicSharedMemorySize, GEMM_SMEM);
    cudaFuncSetAttribute(k_gemm_mma2, cudaFuncAttributeMaxDynamicSharedMemorySize, GEMM2_SMEM);

    const int T = 256;
    int nbN  = (N + T - 1) / T;
    int nbE  = (E + T - 1) / T;
    int nbS  = (N + 1023) / 1024;
    int nbW  = (N * 32 + T - 1) / T;
    int nbPW = (P * 32 + T - 1) / T;
    int nbG  = (N + 127) / 128;
    const int WSZ = DDIM * DDIM;

    k_setup<<<nbN, T>>>(W1, W2, lp_w1, wt, N);              // 0
    k_hist<<<nbE, T>>>(edst, E);                            // 1
    k_scan1<<<nbS, 1024>>>(N);                              // 2
    k_gemm_mma<<<nbG, 512, GEMM_SMEM>>>(embed, nullptr,     // 3 (profiled)
                                        wt + 0 * WSZ, hbuf, a_src1, a_dst1, N);
    k_scan2<<<1, 128>>>(nbS);                               // 4
    k_scan3<<<nbS, 1024>>>(N, E);                           // 5
    k_scatter<<<nbE, T>>>(esrc, edst, E);                   // 6

    k_edgeagg<<<nbW, T>>>(hbuf, embed, xbuf, N);            // 7

    k_gemm_mma<<<nbG, 512, GEMM_SMEM>>>(nullptr, xbuf,      // 8
                                        wt + 1 * WSZ, hbuf, a_src2, a_dst2, N);
    k_edgeagg<<<nbW, T>>>(hbuf, nullptr, xbuf, N);          // 9

    k_gemm_mma2<<<nbG, 512, GEMM2_SMEM>>>(xbuf,             // 10
                                          wt + 2 * WSZ, wt + 3 * WSZ,
                                          ub, vb, N);
    k_pairs<<<nbPW, T>>>(lsrc, ldst, lp_b1, lp_w2, lp_b2, out, P);  // 11
}

// round 14
// speedup vs baseline: 1.5799x; 1.0066x over previous
#include <cuda_runtime.h>
#include <cuda_bf16.h>
#include <cuda_fp16.h>
#include <math.h>
#include <stdint.h>

#define NMAX 100000
#define EMAX 1600000
#define DDIM 128

// ---------------- scratch ----------------
__device__ __half g_h [NMAX * DDIM];
__device__ __half g_x [NMAX * DDIM];
__device__ __half g_u [NMAX * DDIM];
__device__ __half g_v [NMAX * DDIM];
__device__ __half g_wt[4 * DDIM * DDIM];
__device__ float4 g_asrc[NMAX];
__device__ float4 g_adst[NMAX];
__device__ float4 g_ew  [EMAX];
__device__ int g_deg   [NMAX];
__device__ int g_rowptr[NMAX + 1];
__device__ int g_cursor[NMAX];
__device__ int g_col   [EMAX];
__device__ int g_bsums [1024];

__device__ __forceinline__ uint32_t smem_to_u32(const void* p) {
    uint32_t a;
    asm("{ .reg .u64 t; cvta.to.shared.u64 t, %1; cvt.u32.u64 %0, t; }" : "=r"(a) : "l"(p));
    return a;
}
#define SW128(off) ((off) ^ (((off) >> 3) & 0x70))

#define LDSM4(r0, r1, r2, r3, addr) \
    asm volatile("ldmatrix.sync.aligned.m8n8.x4.shared.b16 {%0,%1,%2,%3}, [%4];" \
        : "=r"(r0), "=r"(r1), "=r"(r2), "=r"(r3) : "r"(addr))

__device__ __forceinline__ void mma16816(float* d, const uint32_t* a, const uint32_t* b) {
    asm volatile(
        "mma.sync.aligned.m16n8k16.row.col.f32.f16.f16.f32 "
        "{%0,%1,%2,%3},{%4,%5,%6,%7},{%8,%9},{%0,%1,%2,%3};"
        : "+f"(d[0]), "+f"(d[1]), "+f"(d[2]), "+f"(d[3])
        : "r"(a[0]), "r"(a[1]), "r"(a[2]), "r"(a[3]), "r"(b[0]), "r"(b[1]));
}

// ---------------- setup ----------------
__device__ __forceinline__ void wconv_one(const float* __restrict__ W,
                                          __half* __restrict__ wt, int i) {
    int nn = i >> 6;
    int kp = (i & 63) * 2;
    float x0 = W[(size_t)kp * 128 + nn];
    float x1 = W[(size_t)(kp + 1) * 128 + nn];
    reinterpret_cast<__half2*>(wt)[i] = __floats2half2_rn(x0, x1);
}

__global__ void k_setup(const float* __restrict__ W1, const float* __restrict__ W2,
                        const float* __restrict__ lpw1,
                        __half* __restrict__ wt, int n) {
    const int WSZ = DDIM * DDIM;
    int i = blockIdx.x * blockDim.x + threadIdx.x;
    if (i < n) g_deg[i] = 0;
    if (i < 8192)       wconv_one(W1,               wt + 0 * WSZ, i);
    else if (i < 16384) wconv_one(W2,               wt + 1 * WSZ, i - 8192);
    else if (i < 24576) wconv_one(lpw1,             wt + 2 * WSZ, i - 16384);
    else if (i < 32768) wconv_one(lpw1 + 128 * 128, wt + 3 * WSZ, i - 24576);
}

// ---------------- CSR build ----------------
__global__ void k_hist(const int* __restrict__ dst, int e) {
    int i = blockIdx.x * blockDim.x + threadIdx.x;
    if (i < e) atomicAdd(&g_deg[dst[i]], 1);
}
__global__ void k_scan1(int n) {
    __shared__ int ws[32];
    int tid = threadIdx.x;
    int lane = tid & 31, w = tid >> 5;
    int i = blockIdx.x * 1024 + tid;
    int v = (i < n) ? g_deg[i] : 0;
    int x = v;
#pragma unroll
    for (int o = 1; o < 32; o <<= 1) {
        int t = __shfl_up_sync(0xffffffffu, x, o);
        if (lane >= o) x += t;
    }
    if (lane == 31) ws[w] = x;
    __syncthreads();
    if (w == 0) {
        int t = ws[lane];
        int s = t;
#pragma unroll
        for (int o = 1; o < 32; o <<= 1) {
            int q = __shfl_up_sync(0xffffffffu, s, o);
            if (lane >= o) s += q;
        }
        ws[lane] = s - t;
    }
    __syncthreads();
    int incl = x + ws[w];
    if (i < n) g_rowptr[i] = incl - v;
    if (tid == 1023) g_bsums[blockIdx.x] = incl;
}
__global__ void k_scan2(int nb) {
    __shared__ int wsum[4];
    int tid = threadIdx.x;
    int lane = tid & 31, w = tid >> 5;
    int v = (tid < nb) ? g_bsums[tid] : 0;
    int x = v;
#pragma unroll
    for (int o = 1; o < 32; o <<= 1) {
        int t = __shfl_up_sync(0xffffffffu, x, o);
        if (lane >= o) x += t;
    }
    if (lane == 31) wsum[w] = x;
    __syncthreads();
    int add = 0;
#pragma unroll
    for (int j = 0; j < 4; j++) add += (j < w) ? wsum[j] : 0;
    if (tid < nb) g_bsums[tid] = x - v + add;
}
__global__ void k_scan3(int n, int e) {
    int i = blockIdx.x * 1024 + threadIdx.x;
    if (i < n) {
        int v = g_rowptr[i] + g_bsums[blockIdx.x];
        g_rowptr[i] = v;
        g_cursor[i] = v;
    }
    if (i == 0) g_rowptr[n] = e;
}
__global__ void k_scatter(const int* __restrict__ src, const int* __restrict__ dst, int e) {
    int i = blockIdx.x * blockDim.x + threadIdx.x;
    if (i < e) {
        int d = dst[i];
        int slot = atomicAdd(&g_cursor[d], 1);
        g_col[slot] = src[i];
    }
}

// ---------------- fp16 HMMA GEMM, block 64x128, 256 threads, 2 CTA/SM ------
// smem: A 16KB + B 32KB = 48KB
#define GEMM_SMEM 49152

__global__ void __launch_bounds__(256, 2) k_gemm_mma(
    const float* __restrict__ Af,
    const __half* __restrict__ Ax,
    const __half* __restrict__ B,
    __half* __restrict__ C,
    const float* __restrict__ a_src, const float* __restrict__ a_dst, int n)
{
    extern __shared__ char smem[];
    __shared__ float sAl[64][4];
    __shared__ float sDl[64][4];
    uint32_t sb = smem_to_u32(smem);
    const uint32_t sA = sb;
    const uint32_t sB = sb + 16384;

    int tid = threadIdx.x;
    int wid = tid >> 5, lane = tid & 31;
    int wm = wid & 1, wn = wid >> 1;   // 2m x 4n
    int row0 = blockIdx.x * 64;

    if (tid < 64) {
        *reinterpret_cast<float4*>(&sAl[tid][0]) = make_float4(0.f, 0.f, 0.f, 0.f);
        *reinterpret_cast<float4*>(&sDl[tid][0]) = make_float4(0.f, 0.f, 0.f, 0.f);
    }

    float acc[2][4][4];
#pragma unroll
    for (int i = 0; i < 2; i++)
#pragma unroll
        for (int j = 0; j < 4; j++)
#pragma unroll
            for (int q = 0; q < 4; q++) acc[i][j][q] = 0.f;

    const uint4 zero4 = make_uint4(0, 0, 0, 0);

    // A: 64 rows x 128 k fp16 = 1024 uint4 (4 iters)
#pragma unroll
    for (int t = 0; t < 4; t++) {
        int i = tid + t * 256;
        int r = i >> 4;
        int o = i & 15;
        int kh = o >> 3, oo = o & 7;
        uint32_t soff = (uint32_t)(kh * 8192) + SW128((uint32_t)(r * 128 + oo * 16));
        size_t elem = (size_t)(row0 + r) * 128 + kh * 64 + oo * 8;
        bool av = (row0 + r) < n;
        uint4 va;
        if (Af) {
            float4 f0 = make_float4(0.f, 0.f, 0.f, 0.f), f1 = f0;
            if (av) {
                f0 = *reinterpret_cast<const float4*>(&Af[elem]);
                f1 = *reinterpret_cast<const float4*>(&Af[elem + 4]);
            }
            __half2 h0 = __floats2half2_rn(f0.x, f0.y);
            __half2 h1 = __floats2half2_rn(f0.z, f0.w);
            __half2 h2 = __floats2half2_rn(f1.x, f1.y);
            __half2 h3 = __floats2half2_rn(f1.z, f1.w);
            va = make_uint4(*(uint32_t*)&h0, *(uint32_t*)&h1, *(uint32_t*)&h2, *(uint32_t*)&h3);
        } else {
            va = av ? reinterpret_cast<const uint4*>(Ax)[elem >> 3] : zero4;
        }
        *reinterpret_cast<uint4*>(smem + (sA - sb) + soff) = va;
    }
    // B: 128 rows x 128 k fp16 = 2048 uint4 (8 iters)
#pragma unroll
    for (int t = 0; t < 8; t++) {
        int i = tid + t * 256;
        int r = i >> 4;
        int o = i & 15;
        int kh = o >> 3, oo = o & 7;
        uint32_t soff = (uint32_t)(kh * 16384) + SW128((uint32_t)(r * 128 + oo * 16));
        size_t bidx = ((size_t)r * 128 + kh * 64 + oo * 8) >> 3;
        *reinterpret_cast<uint4*>(smem + (sB - sb) + soff) = reinterpret_cast<const uint4*>(B)[bidx];
    }
    __syncthreads();

#pragma unroll
    for (int kh = 0; kh < 2; kh++) {
        uint32_t hoffA = (uint32_t)(kh * 8192);
        uint32_t hoffB = (uint32_t)(kh * 16384);
#pragma unroll
        for (int kk = 0; kk < 4; kk++) {
            int lr = lane & 15;
            int kin = kk * 16 + ((lane >> 4) << 3);
            uint32_t af[2][4], bf[2][4];
#pragma unroll
            for (int mf = 0; mf < 2; mf++) {
                uint32_t off = hoffA + SW128((uint32_t)((wm * 32 + mf * 16 + lr) * 128 + kin * 2));
                LDSM4(af[mf][0], af[mf][1], af[mf][2], af[mf][3], sA + off);
            }
#pragma unroll
            for (int nf = 0; nf < 2; nf++) {
                uint32_t off = hoffB + SW128((uint32_t)((wn * 32 + nf * 16 + lr) * 128 + kin * 2));
                LDSM4(bf[nf][0], bf[nf][1], bf[nf][2], bf[nf][3], sB + off);
            }
#pragma unroll
            for (int mf = 0; mf < 2; mf++) {
#pragma unroll
                for (int ns = 0; ns < 4; ns++) {
                    int g = ns >> 1, od = ns & 1;
                    uint32_t bb[2] = { bf[g][od], bf[g][od + 2] };
                    mma16816(acc[mf][ns], af[mf], bb);
                }
            }
        }
    }

    int qrow = lane >> 2, qcol = (lane & 3) * 2;

    // fused alpha partial dots (fp32)
    {
        float2 s2[4], d2[4];
#pragma unroll
        for (int ns = 0; ns < 4; ns++) {
            int c = wn * 32 + ns * 8 + qcol;
            s2[ns] = *reinterpret_cast<const float2*>(&a_src[c]);
            d2[ns] = *reinterpret_cast<const float2*>(&a_dst[c]);
        }
#pragma unroll
        for (int mf = 0; mf < 2; mf++) {
            int rl = wm * 32 + mf * 16 + qrow;
            float pa0 = 0.f, pd0 = 0.f, pa1 = 0.f, pd1 = 0.f;
#pragma unroll
            for (int ns = 0; ns < 4; ns++) {
                pa0 += acc[mf][ns][0] * s2[ns].x + acc[mf][ns][1] * s2[ns].y;
                pd0 += acc[mf][ns][0] * d2[ns].x + acc[mf][ns][1] * d2[ns].y;
                pa1 += acc[mf][ns][2] * s2[ns].x + acc[mf][ns][3] * s2[ns].y;
                pd1 += acc[mf][ns][2] * d2[ns].x + acc[mf][ns][3] * d2[ns].y;
            }
            atomicAdd(&sAl[rl][wn], pa0);     atomicAdd(&sDl[rl][wn], pd0);
            atomicAdd(&sAl[rl + 8][wn], pa1); atomicAdd(&sDl[rl + 8][wn], pd1);
        }
    }

    // h store fp16
#pragma unroll
    for (int mf = 0; mf < 2; mf++) {
#pragma unroll
        for (int ns = 0; ns < 4; ns++) {
            int r0 = row0 + wm * 32 + mf * 16 + qrow;
            int c0 = wn * 32 + ns * 8 + qcol;
            if (r0 < n) {
                __half2 hv = __floats2half2_rn(acc[mf][ns][0], acc[mf][ns][1]);
                *reinterpret_cast<uint32_t*>(&C[(size_t)r0 * 128 + c0]) = *(uint32_t*)&hv;
            }
            if (r0 + 8 < n) {
                __half2 hv = __floats2half2_rn(acc[mf][ns][2], acc[mf][ns][3]);
                *reinterpret_cast<uint32_t*>(&C[(size_t)(r0 + 8) * 128 + c0]) = *(uint32_t*)&hv;
            }
        }
    }

    __syncthreads();
    if (tid < 64 && row0 + tid < n) {
        g_asrc[row0 + tid] = *reinterpret_cast<float4*>(&sAl[tid][0]);
        g_adst[row0 + tid] = *reinterpret_cast<float4*>(&sDl[tid][0]);
    }
}

// ---------------- dual-B fp16 GEMM, block 64x128, 256 threads --------------
// smem: A 16KB + B1 32KB + B2 32KB = 80KB -> 2 CTA/SM
#define GEMM2_SMEM 81920

__global__ void __launch_bounds__(256, 2) k_gemm_mma2(
    const __half* __restrict__ Ax,
    const __half* __restrict__ B1, const __half* __restrict__ B2,
    __half* __restrict__ C1, __half* __restrict__ C2, int n)
{
    extern __shared__ char smem[];
    uint32_t sb = smem_to_u32(smem);
    const uint32_t sA  = sb;
    const uint32_t sB1 = sb + 16384;
    const uint32_t sB2 = sb + 49152;

    int tid = threadIdx.x;
    int wid = tid >> 5, lane = tid & 31;
    int wm = wid & 1, wn = wid >> 1;
    int row0 = blockIdx.x * 64;

    const uint4 zero4 = make_uint4(0, 0, 0, 0);

    float acc1[2][4][4], acc2[2][4][4];
#pragma unroll
    for (int i = 0; i < 2; i++)
#pragma unroll
        for (int j = 0; j < 4; j++)
#pragma unroll
            for (int q = 0; q < 4; q++) { acc1[i][j][q] = 0.f; acc2[i][j][q] = 0.f; }

#pragma unroll
    for (int t = 0; t < 4; t++) {
        int i = tid + t * 256;
        int r = i >> 4;
        int o = i & 15;
        int kh = o >> 3, oo = o & 7;
        uint32_t soff = (uint32_t)(kh * 8192) + SW128((uint32_t)(r * 128 + oo * 16));
        size_t elem = (size_t)(row0 + r) * 128 + kh * 64 + oo * 8;
        bool av = (row0 + r) < n;
        uint4 va = av ? reinterpret_cast<const uint4*>(Ax)[elem >> 3] : zero4;
        *reinterpret_cast<uint4*>(smem + (sA - sb) + soff) = va;
    }
#pragma unroll
    for (int t = 0; t < 8; t++) {
        int i = tid + t * 256;
        int r = i >> 4;
        int o = i & 15;
        int kh = o >> 3, oo = o & 7;
        uint32_t soff = (uint32_t)(kh * 16384) + SW128((uint32_t)(r * 128 + oo * 16));
        size_t bidx = ((size_t)r * 128 + kh * 64 + oo * 8) >> 3;
        *reinterpret_cast<uint4*>(smem + (sB1 - sb) + soff) = reinterpret_cast<const uint4*>(B1)[bidx];
        *reinterpret_cast<uint4*>(smem + (sB2 - sb) + soff) = reinterpret_cast<const uint4*>(B2)[bidx];
    }
    __syncthreads();

#pragma unroll
    for (int kh = 0; kh < 2; kh++) {
        uint32_t hoffA = (uint32_t)(kh * 8192);
        uint32_t hoffB = (uint32_t)(kh * 16384);
#pragma unroll
        for (int kk = 0; kk < 4; kk++) {
            int lr = lane & 15;
            int kin = kk * 16 + ((lane >> 4) << 3);
            uint32_t af[2][4], b1f[2][4], b2f[2][4];
#pragma unroll
            for (int mf = 0; mf < 2; mf++) {
                uint32_t off = hoffA + SW128((uint32_t)((wm * 32 + mf * 16 + lr) * 128 + kin * 2));
                LDSM4(af[mf][0], af[mf][1], af[mf][2], af[mf][3], sA + off);
            }
#pragma unroll
            for (int nf = 0; nf < 2; nf++) {
                uint32_t off = hoffB + SW128((uint32_t)((wn * 32 + nf * 16 + lr) * 128 + kin * 2));
                LDSM4(b1f[nf][0], b1f[nf][1], b1f[nf][2], b1f[nf][3], sB1 + off);
                LDSM4(b2f[nf][0], b2f[nf][1], b2f[nf][2], b2f[nf][3], sB2 + off);
            }
#pragma unroll
            for (int mf = 0; mf < 2; mf++) {
#pragma unroll
                for (int ns = 0; ns < 4; ns++) {
                    int g = ns >> 1, od = ns & 1;
                    uint32_t bb1[2] = { b1f[g][od], b1f[g][od + 2] };
                    uint32_t bb2[2] = { b2f[g][od], b2f[g][od + 2] };
                    mma16816(acc1[mf][ns], af[mf], bb1);
                    mma16816(acc2[mf][ns], af[mf], bb2);
                }
            }
        }
    }

    int qrow = lane >> 2, qcol = (lane & 3) * 2;
#pragma unroll
    for (int mf = 0; mf < 2; mf++) {
#pragma unroll
        for (int ns = 0; ns < 4; ns++) {
            int r0 = row0 + wm * 32 + mf * 16 + qrow;
            int c0 = wn * 32 + ns * 8 + qcol;
            if (r0 < n) {
                __half2 h1 = __floats2half2_rn(acc1[mf][ns][0], acc1[mf][ns][1]);
                __half2 h2 = __floats2half2_rn(acc2[mf][ns][0], acc2[mf][ns][1]);
                *reinterpret_cast<uint32_t*>(&C1[(size_t)r0 * 128 + c0]) = *(uint32_t*)&h1;
                *reinterpret_cast<uint32_t*>(&C2[(size_t)r0 * 128 + c0]) = *(uint32_t*)&h2;
            }
            if (r0 + 8 < n) {
                __half2 h1 = __floats2half2_rn(acc1[mf][ns][2], acc1[mf][ns][3]);
                __half2 h2 = __floats2half2_rn(acc2[mf][ns][2], acc2[mf][ns][3]);
                *reinterpret_cast<uint32_t*>(&C1[(size_t)(r0 + 8) * 128 + c0]) = *(uint32_t*)&h1;
                *reinterpret_cast<uint32_t*>(&C2[(size_t)(r0 + 8) * 128 + c0]) = *(uint32_t*)&h2;
            }
        }
    }
}

// ---------------- warp helpers ----------------
__device__ __forceinline__ float warp_sum(float v) {
#pragma unroll
    for (int o = 16; o; o >>= 1) v += __shfl_xor_sync(0xffffffffu, v, o);
    return v;
}

__device__ __forceinline__ float lrelu(float x) { return x >= 0.f ? x : 0.2f * x; }
__device__ __forceinline__ float elu(float x)  { return x > 0.f ? x : expm1f(x); }

// ---------------- fused GAT aggregation ----------------
__global__ void k_edgeagg(const __half* __restrict__ h,
                          const float* __restrict__ xprev_f,
                          __half* __restrict__ x, int n)
{
    __shared__ int   sidx[8][32];
    __shared__ float4 swt[8][32];

    int w = threadIdx.x >> 5;
    int gw = (blockIdx.x * blockDim.x + threadIdx.x) >> 5;
    int lane = threadIdx.x & 31;
    if (gw >= n) return;

    int base = g_rowptr[gw];
    int deg  = g_rowptr[gw + 1] - base;
    float4 ad = g_adst[gw];
    float4 acc = make_float4(0.f, 0.f, 0.f, 0.f);
    int hsel = lane >> 3;

    if (deg <= 32) {
        int myidx = 0;
        float p0 = 0.f, p1 = 0.f, p2 = 0.f, p3 = 0.f;
        if (lane < deg) {
            myidx = g_col[base + lane];
            float4 as = g_asrc[myidx];
            p0 = expf(fminf(lrelu(as.x + ad.x), 75.f));
            p1 = expf(fminf(lrelu(as.y + ad.y), 75.f));
            p2 = expf(fminf(lrelu(as.z + ad.z), 75.f));
            p3 = expf(fminf(lrelu(as.w + ad.w), 75.f));
        }
        float i0 = 1.f / (warp_sum(p0) + 1e-10f);
        float i1 = 1.f / (warp_sum(p1) + 1e-10f);
        float i2 = 1.f / (warp_sum(p2) + 1e-10f);
        float i3 = 1.f / (warp_sum(p3) + 1e-10f);
        sidx[w][lane] = myidx;
        swt[w][lane] = make_float4(p0 * i0, p1 * i1, p2 * i2, p3 * i3);
        __syncwarp();
#pragma unroll 4
        for (int j = 0; j < deg; j++) {
            int s = sidx[w][j];
            float wj = reinterpret_cast<const float*>(&swt[w][j])[hsel];
            uint2 raw = *reinterpret_cast<const uint2*>(&h[(size_t)s * 128 + 4 * lane]);
            float2 f01 = __half22float2(*reinterpret_cast<const __half2*>(&raw.x));
            float2 f23 = __half22float2(*reinterpret_cast<const __half2*>(&raw.y));
            acc.x += f01.x * wj;
            acc.y += f01.y * wj;
            acc.z += f23.x * wj;
            acc.w += f23.y * wj;
        }
    } else {
        float s0 = 0.f, s1 = 0.f, s2 = 0.f, s3 = 0.f;
        for (int i = lane; i < deg; i += 32) {
            int s = g_col[base + i];
            float4 as = g_asrc[s];
            float p0 = expf(fminf(lrelu(as.x + ad.x), 75.f));
            float p1 = expf(fminf(lrelu(as.y + ad.y), 75.f));
            float p2 = expf(fminf(lrelu(as.z + ad.z), 75.f));
            float p3 = expf(fminf(lrelu(as.w + ad.w), 75.f));
            g_ew[base + i] = make_float4(p0, p1, p2, p3);
            s0 += p0; s1 += p1; s2 += p2; s3 += p3;
        }
        s0 = warp_sum(s0); s1 = warp_sum(s1); s2 = warp_sum(s2); s3 = warp_sum(s3);
        float i0 = 1.f / (s0 + 1e-10f);
        float i1 = 1.f / (s1 + 1e-10f);
        float i2 = 1.f / (s2 + 1e-10f);
        float i3 = 1.f / (s3 + 1e-10f);

        for (int bi = 0; bi < deg; bi += 32) {
            int cnt = min(32, deg - bi);
            if (lane < cnt) {
                sidx[w][lane] = g_col[base + bi + lane];
                float4 p = g_ew[base + bi + lane];
                swt[w][lane] = make_float4(p.x * i0, p.y * i1, p.z * i2, p.w * i3);
            }
            __syncwarp();
#pragma unroll 4
            for (int j = 0; j < cnt; j++) {
                int s = sidx[w][j];
                float wj = reinterpret_cast<const float*>(&swt[w][j])[hsel];
                uint2 raw = *reinterpret_cast<const uint2*>(&h[(size_t)s * 128 + 4 * lane]);
                float2 f01 = __half22float2(*reinterpret_cast<const __half2*>(&raw.x));
                float2 f23 = __half22float2(*reinterpret_cast<const __half2*>(&raw.y));
                acc.x += f01.x * wj;
                acc.y += f01.y * wj;
                acc.z += f23.x * wj;
                acc.w += f23.y * wj;
            }
            __syncwarp();
        }
    }

    size_t o = (size_t)gw * 128 + 4 * lane;
    float4 xp;
    if (xprev_f) {
        xp = *reinterpret_cast<const float4*>(&xprev_f[o]);
    } else {
        uint2 rx = *reinterpret_cast<const uint2*>(&x[o]);
        float2 x01 = __half22float2(*reinterpret_cast<const __half2*>(&rx.x));
        float2 x23 = __half22float2(*reinterpret_cast<const __half2*>(&rx.y));
        xp = make_float4(x01.x, x01.y, x23.x, x23.y);
    }
    float4 v = make_float4(elu(acc.x) + xp.x, elu(acc.y) + xp.y,
                           elu(acc.z) + xp.z, elu(acc.w) + xp.w);
    {
        __half2 h0 = __floats2half2_rn(v.x, v.y);
        __half2 h1 = __floats2half2_rn(v.z, v.w);
        uint2 pv = make_uint2(*(uint32_t*)&h0, *(uint32_t*)&h1);
        *reinterpret_cast<uint2*>(&x[o]) = pv;
    }
}

// ---------------- pair epilogue ----------------
__global__ void k_pairs(const int* __restrict__ lsrc, const int* __restrict__ ldst,
                        const float* __restrict__ b1, const float* __restrict__ w2,
                        const float* __restrict__ b2, float* __restrict__ out, int p)
{
    int gw = (blockIdx.x * blockDim.x + threadIdx.x) >> 5;
    int lane = threadIdx.x & 31;
    if (gw >= p) return;
    int k = 4 * lane;
    uint2 ru = *reinterpret_cast<const uint2*>(&g_u[(size_t)lsrc[gw] * 128 + k]);
    uint2 rv = *reinterpret_cast<const uint2*>(&g_v[(size_t)ldst[gw] * 128 + k]);
    float2 u01 = __half22float2(*reinterpret_cast<const __half2*>(&ru.x));
    float2 u23 = __half22float2(*reinterpret_cast<const __half2*>(&ru.y));
    float2 v01 = __half22float2(*reinterpret_cast<const __half2*>(&rv.x));
    float2 v23 = __half22float2(*reinterpret_cast<const __half2*>(&rv.y));
    float4 b = *reinterpret_cast<const float4*>(&b1[k]);
    float4 w = *reinterpret_cast<const float4*>(&w2[k]);
    float t = fmaxf(u01.x + v01.x + b.x, 0.f) * w.x
            + fmaxf(u01.y + v01.y + b.y, 0.f) * w.y
            + fmaxf(u23.x + v23.x + b.z, 0.f) * w.z
            + fmaxf(u23.y + v23.y + b.w, 0.f) * w.w;
    t = warp_sum(t);
    if (lane == 0) out[gw] = t + b2[0];
}

// ---------------- driver ----------------
extern "C" void kernel_launch(void* const* d_in, const int* in_sizes, int n_in,
                              void* d_out, int out_size)
{
    const float* embed  = (const float*)d_in[0];
    const float* W1     = (const float*)d_in[1];
    const float* a_src1 = (const float*)d_in[2];
    const float* a_dst1 = (const float*)d_in[3];
    const float* W2     = (const float*)d_in[4];
    const float* a_src2 = (const float*)d_in[5];
    const float* a_dst2 = (const float*)d_in[6];
    const float* lp_w1  = (const float*)d_in[7];
    const float* lp_b1  = (const float*)d_in[8];
    const float* lp_w2  = (const float*)d_in[9];
    const float* lp_b2  = (const float*)d_in[10];
    const int*   eidx   = (const int*)d_in[11];
    const int*   lsrc   = (const int*)d_in[12];
    const int*   ldst   = (const int*)d_in[13];
    float* out = (float*)d_out;

    const int N = in_sizes[0] / DDIM;
    const int E = in_sizes[11] / 2;
    const int P = in_sizes[12];
    const int* esrc = eidx;
    const int* edst = eidx + E;

    __half* hbuf; cudaGetSymbolAddress((void**)&hbuf, g_h);
    __half* xbuf; cudaGetSymbolAddress((void**)&xbuf, g_x);
    __half* ub;   cudaGetSymbolAddress((void**)&ub,   g_u);
    __half* vb;   cudaGetSymbolAddress((void**)&vb,   g_v);
    __half* wt;   cudaGetSymbolAddress((void**)&wt,   g_wt);

    cudaFuncSetAttribute(k_gemm_mma,  cudaFuncAttributeMaxDynamicSharedMemorySize, GEMM_SMEM);
    cudaFuncSetAttribute(k_gemm_mma2, cudaFuncAttributeMaxDynamicSharedMemorySize, GEMM2_SMEM);

    const int T = 256;
    int nbN  = (N + T - 1) / T;
    int nbE  = (E + T - 1) / T;
    int nbS  = (N + 1023) / 1024;
    int nbW  = (N * 32 + T - 1) / T;
    int nbPW = (P * 32 + T - 1) / T;
    int nbG  = (N + 63) / 64;
    const int WSZ = DDIM * DDIM;

    k_setup<<<nbN, T>>>(W1, W2, lp_w1, wt, N);              // 0
    k_hist<<<nbE, T>>>(edst, E);                            // 1
    k_scan1<<<nbS, 1024>>>(N);                              // 2
    k_gemm_mma<<<nbG, 256, GEMM_SMEM>>>(embed, nullptr,     // 3 (profiled)
                                        wt + 0 * WSZ, hbuf, a_src1, a_dst1, N);
    k_scan2<<<1, 128>>>(nbS);                               // 4
    k_scan3<<<nbS, 1024>>>(N, E);                           // 5
    k_scatter<<<nbE, T>>>(esrc, edst, E);                   // 6

    k_edgeagg<<<nbW, T>>>(hbuf, embed, xbuf, N);            // 7

    k_gemm_mma<<<nbG, 256, GEMM_SMEM>>>(nullptr, xbuf,      // 8
                                        wt + 1 * WSZ, hbuf, a_src2, a_dst2, N);
    k_edgeagg<<<nbW, T>>>(hbuf, nullptr, xbuf, N);          // 9

    k_gemm_mma2<<<nbG, 256, GEMM2_SMEM>>>(xbuf,             // 10
                                          wt + 2 * WSZ, wt + 3 * WSZ,
                                          ub, vb, N);
    k_pairs<<<nbPW, T>>>(lsrc, ldst, lp_b1, lp_w2, lp_b2, out, P);  // 11
}

// round 15
// speedup vs baseline: 1.7461x; 1.1052x over previous
#include <cuda_runtime.h>
#include <cuda_bf16.h>
#include <cuda_fp16.h>
#include <math.h>
#include <stdint.h>

#define NMAX 100000
#define EMAX 1600000
#define DDIM 128

// ---------------- scratch ----------------
__device__ __half g_h [NMAX * DDIM];
__device__ __half g_x [NMAX * DDIM];
__device__ __half g_u [NMAX * DDIM];
__device__ __half g_v [NMAX * DDIM];
__device__ __half g_wt[4 * DDIM * DDIM];
__device__ float4 g_asrc[NMAX];
__device__ float4 g_adst[NMAX];
__device__ float4 g_ew  [EMAX];
__device__ int g_deg   [NMAX];
__device__ int g_rowptr[NMAX + 1];
__device__ int g_cursor[NMAX];
__device__ int g_col   [EMAX];
__device__ int g_bsums [1024];

__device__ __forceinline__ uint32_t smem_to_u32(const void* p) {
    uint32_t a;
    asm("{ .reg .u64 t; cvta.to.shared.u64 t, %1; cvt.u32.u64 %0, t; }" : "=r"(a) : "l"(p));
    return a;
}
#define SW128(off) ((off) ^ (((off) >> 3) & 0x70))

#define CP_ASYNC16(dst, src, sz) \
    asm volatile("cp.async.cg.shared.global [%0], [%1], 16, %2;" \
        :: "r"(dst), "l"(src), "r"(sz))
#define CP_COMMIT() asm volatile("cp.async.commit_group;" ::: "memory")
#define CP_WAIT0()  asm volatile("cp.async.wait_group 0;" ::: "memory")

#define LDSM4(r0, r1, r2, r3, addr) \
    asm volatile("ldmatrix.sync.aligned.m8n8.x4.shared.b16 {%0,%1,%2,%3}, [%4];" \
        : "=r"(r0), "=r"(r1), "=r"(r2), "=r"(r3) : "r"(addr))

__device__ __forceinline__ void mma16816(float* d, const uint32_t* a, const uint32_t* b) {
    asm volatile(
        "mma.sync.aligned.m16n8k16.row.col.f32.f16.f16.f32 "
        "{%0,%1,%2,%3},{%4,%5,%6,%7},{%8,%9},{%0,%1,%2,%3};"
        : "+f"(d[0]), "+f"(d[1]), "+f"(d[2]), "+f"(d[3])
        : "r"(a[0]), "r"(a[1]), "r"(a[2]), "r"(a[3]), "r"(b[0]), "r"(b[1]));
}

// ---------------- setup ----------------
__device__ __forceinline__ void wconv_one(const float* __restrict__ W,
                                          __half* __restrict__ wt, int i) {
    int nn = i >> 6;
    int kp = (i & 63) * 2;
    float x0 = W[(size_t)kp * 128 + nn];
    float x1 = W[(size_t)(kp + 1) * 128 + nn];
    reinterpret_cast<__half2*>(wt)[i] = __floats2half2_rn(x0, x1);
}

__global__ void k_setup(const float* __restrict__ W1, const float* __restrict__ W2,
                        const float* __restrict__ lpw1,
                        __half* __restrict__ wt, int n) {
    const int WSZ = DDIM * DDIM;
    int i = blockIdx.x * blockDim.x + threadIdx.x;
    if (i < n) g_deg[i] = 0;
    if (i < 8192)       wconv_one(W1,               wt + 0 * WSZ, i);
    else if (i < 16384) wconv_one(W2,               wt + 1 * WSZ, i - 8192);
    else if (i < 24576) wconv_one(lpw1,             wt + 2 * WSZ, i - 16384);
    else if (i < 32768) wconv_one(lpw1 + 128 * 128, wt + 3 * WSZ, i - 24576);
}

// ---------------- CSR build ----------------
__global__ void k_hist(const int* __restrict__ dst, int e) {
    int i = blockIdx.x * blockDim.x + threadIdx.x;
    if (i < e) atomicAdd(&g_deg[dst[i]], 1);
}
__global__ void k_scan1(int n) {
    __shared__ int ws[32];
    int tid = threadIdx.x;
    int lane = tid & 31, w = tid >> 5;
    int i = blockIdx.x * 1024 + tid;
    int v = (i < n) ? g_deg[i] : 0;
    int x = v;
#pragma unroll
    for (int o = 1; o < 32; o <<= 1) {
        int t = __shfl_up_sync(0xffffffffu, x, o);
        if (lane >= o) x += t;
    }
    if (lane == 31) ws[w] = x;
    __syncthreads();
    if (w == 0) {
        int t = ws[lane];
        int s = t;
#pragma unroll
        for (int o = 1; o < 32; o <<= 1) {
            int q = __shfl_up_sync(0xffffffffu, s, o);
            if (lane >= o) s += q;
        }
        ws[lane] = s - t;
    }
    __syncthreads();
    int incl = x + ws[w];
    if (i < n) g_rowptr[i] = incl - v;
    if (tid == 1023) g_bsums[blockIdx.x] = incl;
}
__global__ void k_scan2(int nb) {
    __shared__ int wsum[4];
    int tid = threadIdx.x;
    int lane = tid & 31, w = tid >> 5;
    int v = (tid < nb) ? g_bsums[tid] : 0;
    int x = v;
#pragma unroll
    for (int o = 1; o < 32; o <<= 1) {
        int t = __shfl_up_sync(0xffffffffu, x, o);
        if (lane >= o) x += t;
    }
    if (lane == 31) wsum[w] = x;
    __syncthreads();
    int add = 0;
#pragma unroll
    for (int j = 0; j < 4; j++) add += (j < w) ? wsum[j] : 0;
    if (tid < nb) g_bsums[tid] = x - v + add;
}
__global__ void k_scan3(int n, int e) {
    int i = blockIdx.x * 1024 + threadIdx.x;
    if (i < n) {
        int v = g_rowptr[i] + g_bsums[blockIdx.x];
        g_rowptr[i] = v;
        g_cursor[i] = v;
    }
    if (i == 0) g_rowptr[n] = e;
}
__global__ void k_scatter(const int* __restrict__ src, const int* __restrict__ dst, int e) {
    int i = blockIdx.x * blockDim.x + threadIdx.x;
    if (i < e) {
        int d = dst[i];
        int slot = atomicAdd(&g_cursor[d], 1);
        g_col[slot] = src[i];
    }
}

// ---------------- fp16 HMMA GEMM, block 64x128, cp.async, 3 CTA/SM ---------
#define GEMM_SMEM 49152

__global__ void __launch_bounds__(256, 3) k_gemm_mma(
    const float* __restrict__ Af,
    const __half* __restrict__ Ax,
    const __half* __restrict__ B,
    __half* __restrict__ C,
    const float* __restrict__ a_src, const float* __restrict__ a_dst, int n)
{
    extern __shared__ char smem[];
    __shared__ float sAl[64][4];
    __shared__ float sDl[64][4];
    uint32_t sb = smem_to_u32(smem);
    const uint32_t sA = sb;
    const uint32_t sB = sb + 16384;

    int tid = threadIdx.x;
    int wid = tid >> 5, lane = tid & 31;
    int wm = wid & 1, wn = wid >> 1;
    int row0 = blockIdx.x * 64;

    if (tid < 64) {
        *reinterpret_cast<float4*>(&sAl[tid][0]) = make_float4(0.f, 0.f, 0.f, 0.f);
        *reinterpret_cast<float4*>(&sDl[tid][0]) = make_float4(0.f, 0.f, 0.f, 0.f);
    }

    float acc[2][4][4];
#pragma unroll
    for (int i = 0; i < 2; i++)
#pragma unroll
        for (int j = 0; j < 4; j++)
#pragma unroll
            for (int q = 0; q < 4; q++) acc[i][j][q] = 0.f;

    // A: 64 rows x 128 k fp16 = 1024 16B chunks (4 iters)
    if (Af) {
#pragma unroll
        for (int t = 0; t < 4; t++) {
            int i = tid + t * 256;
            int r = i >> 4;
            int o = i & 15;
            int kh = o >> 3, oo = o & 7;
            uint32_t soff = (uint32_t)(kh * 8192) + SW128((uint32_t)(r * 128 + oo * 16));
            size_t elem = (size_t)(row0 + r) * 128 + kh * 64 + oo * 8;
            bool av = (row0 + r) < n;
            uint4 va = make_uint4(0, 0, 0, 0);
            if (av) {
                float4 f0 = *reinterpret_cast<const float4*>(&Af[elem]);
                float4 f1 = *reinterpret_cast<const float4*>(&Af[elem + 4]);
                __half2 h0 = __floats2half2_rn(f0.x, f0.y);
                __half2 h1 = __floats2half2_rn(f0.z, f0.w);
                __half2 h2 = __floats2half2_rn(f1.x, f1.y);
                __half2 h3 = __floats2half2_rn(f1.z, f1.w);
                va = make_uint4(*(uint32_t*)&h0, *(uint32_t*)&h1, *(uint32_t*)&h2, *(uint32_t*)&h3);
            }
            *reinterpret_cast<uint4*>(smem + (sA - sb) + soff) = va;
        }
    } else {
#pragma unroll
        for (int t = 0; t < 4; t++) {
            int i = tid + t * 256;
            int r = i >> 4;
            int o = i & 15;
            int kh = o >> 3, oo = o & 7;
            uint32_t soff = (uint32_t)(kh * 8192) + SW128((uint32_t)(r * 128 + oo * 16));
            size_t elem = (size_t)(row0 + r) * 128 + kh * 64 + oo * 8;
            int sz = ((row0 + r) < n) ? 16 : 0;
            CP_ASYNC16(sA + soff, &Ax[elem], sz);
        }
    }
    // B: 2048 16B chunks (8 iters), cp.async
#pragma unroll
    for (int t = 0; t < 8; t++) {
        int i = tid + t * 256;
        int r = i >> 4;
        int o = i & 15;
        int kh = o >> 3, oo = o & 7;
        uint32_t soff = (uint32_t)(kh * 16384) + SW128((uint32_t)(r * 128 + oo * 16));
        CP_ASYNC16(sB + soff, &B[(size_t)r * 128 + kh * 64 + oo * 8], 16);
    }
    CP_COMMIT();
    CP_WAIT0();
    __syncthreads();

#pragma unroll
    for (int kh = 0; kh < 2; kh++) {
        uint32_t hoffA = (uint32_t)(kh * 8192);
        uint32_t hoffB = (uint32_t)(kh * 16384);
#pragma unroll
        for (int kk = 0; kk < 4; kk++) {
            int lr = lane & 15;
            int kin = kk * 16 + ((lane >> 4) << 3);
            uint32_t af[2][4], bf[2][4];
#pragma unroll
            for (int mf = 0; mf < 2; mf++) {
                uint32_t off = hoffA + SW128((uint32_t)((wm * 32 + mf * 16 + lr) * 128 + kin * 2));
                LDSM4(af[mf][0], af[mf][1], af[mf][2], af[mf][3], sA + off);
            }
#pragma unroll
            for (int nf = 0; nf < 2; nf++) {
                uint32_t off = hoffB + SW128((uint32_t)((wn * 32 + nf * 16 + lr) * 128 + kin * 2));
                LDSM4(bf[nf][0], bf[nf][1], bf[nf][2], bf[nf][3], sB + off);
            }
#pragma unroll
            for (int mf = 0; mf < 2; mf++) {
#pragma unroll
                for (int ns = 0; ns < 4; ns++) {
                    int g = ns >> 1, od = ns & 1;
                    uint32_t bb[2] = { bf[g][od], bf[g][od + 2] };
                    mma16816(acc[mf][ns], af[mf], bb);
                }
            }
        }
    }

    int qrow = lane >> 2, qcol = (lane & 3) * 2;

    // fused alpha partial dots (fp32)
    {
        float2 s2[4], d2[4];
#pragma unroll
        for (int ns = 0; ns < 4; ns++) {
            int c = wn * 32 + ns * 8 + qcol;
            s2[ns] = *reinterpret_cast<const float2*>(&a_src[c]);
            d2[ns] = *reinterpret_cast<const float2*>(&a_dst[c]);
        }
#pragma unroll
        for (int mf = 0; mf < 2; mf++) {
            int rl = wm * 32 + mf * 16 + qrow;
            float pa0 = 0.f, pd0 = 0.f, pa1 = 0.f, pd1 = 0.f;
#pragma unroll
            for (int ns = 0; ns < 4; ns++) {
                pa0 += acc[mf][ns][0] * s2[ns].x + acc[mf][ns][1] * s2[ns].y;
                pd0 += acc[mf][ns][0] * d2[ns].x + acc[mf][ns][1] * d2[ns].y;
                pa1 += acc[mf][ns][2] * s2[ns].x + acc[mf][ns][3] * s2[ns].y;
                pd1 += acc[mf][ns][2] * d2[ns].x + acc[mf][ns][3] * d2[ns].y;
            }
            atomicAdd(&sAl[rl][wn], pa0);     atomicAdd(&sDl[rl][wn], pd0);
            atomicAdd(&sAl[rl + 8][wn], pa1); atomicAdd(&sDl[rl + 8][wn], pd1);
        }
    }

    // h store fp16
#pragma unroll
    for (int mf = 0; mf < 2; mf++) {
#pragma unroll
        for (int ns = 0; ns < 4; ns++) {
            int r0 = row0 + wm * 32 + mf * 16 + qrow;
            int c0 = wn * 32 + ns * 8 + qcol;
            if (r0 < n) {
                __half2 hv = __floats2half2_rn(acc[mf][ns][0], acc[mf][ns][1]);
                *reinterpret_cast<uint32_t*>(&C[(size_t)r0 * 128 + c0]) = *(uint32_t*)&hv;
            }
            if (r0 + 8 < n) {
                __half2 hv = __floats2half2_rn(acc[mf][ns][2], acc[mf][ns][3]);
                *reinterpret_cast<uint32_t*>(&C[(size_t)(r0 + 8) * 128 + c0]) = *(uint32_t*)&hv;
            }
        }
    }

    __syncthreads();
    if (tid < 64 && row0 + tid < n) {
        g_asrc[row0 + tid] = *reinterpret_cast<float4*>(&sAl[tid][0]);
        g_adst[row0 + tid] = *reinterpret_cast<float4*>(&sDl[tid][0]);
    }
}

// ---------------- dual-B fp16 GEMM, cp.async, 2 CTA/SM ---------------------
#define GEMM2_SMEM 81920

__global__ void __launch_bounds__(256, 2) k_gemm_mma2(
    const __half* __restrict__ Ax,
    const __half* __restrict__ B1, const __half* __restrict__ B2,
    __half* __restrict__ C1, __half* __restrict__ C2, int n)
{
    extern __shared__ char smem[];
    uint32_t sb = smem_to_u32(smem);
    const uint32_t sA  = sb;
    const uint32_t sB1 = sb + 16384;
    const uint32_t sB2 = sb + 49152;

    int tid = threadIdx.x;
    int wid = tid >> 5, lane = tid & 31;
    int wm = wid & 1, wn = wid >> 1;
    int row0 = blockIdx.x * 64;

    float acc1[2][4][4], acc2[2][4][4];
#pragma unroll
    for (int i = 0; i < 2; i++)
#pragma unroll
        for (int j = 0; j < 4; j++)
#pragma unroll
            for (int q = 0; q < 4; q++) { acc1[i][j][q] = 0.f; acc2[i][j][q] = 0.f; }

#pragma unroll
    for (int t = 0; t < 4; t++) {
        int i = tid + t * 256;
        int r = i >> 4;
        int o = i & 15;
        int kh = o >> 3, oo = o & 7;
        uint32_t soff = (uint32_t)(kh * 8192) + SW128((uint32_t)(r * 128 + oo * 16));
        size_t elem = (size_t)(row0 + r) * 128 + kh * 64 + oo * 8;
        int sz = ((row0 + r) < n) ? 16 : 0;
        CP_ASYNC16(sA + soff, &Ax[elem], sz);
    }
#pragma unroll
    for (int t = 0; t < 8; t++) {
        int i = tid + t * 256;
        int r = i >> 4;
        int o = i & 15;
        int kh = o >> 3, oo = o & 7;
        uint32_t soff = (uint32_t)(kh * 16384) + SW128((uint32_t)(r * 128 + oo * 16));
        size_t bidx = (size_t)r * 128 + kh * 64 + oo * 8;
        CP_ASYNC16(sB1 + soff, &B1[bidx], 16);
        CP_ASYNC16(sB2 + soff, &B2[bidx], 16);
    }
    CP_COMMIT();
    CP_WAIT0();
    __syncthreads();

#pragma unroll
    for (int kh = 0; kh < 2; kh++) {
        uint32_t hoffA = (uint32_t)(kh * 8192);
        uint32_t hoffB = (uint32_t)(kh * 16384);
#pragma unroll
        for (int kk = 0; kk < 4; kk++) {
            int lr = lane & 15;
            int kin = kk * 16 + ((lane >> 4) << 3);
            uint32_t af[2][4], b1f[2][4], b2f[2][4];
#pragma unroll
            for (int mf = 0; mf < 2; mf++) {
                uint32_t off = hoffA + SW128((uint32_t)((wm * 32 + mf * 16 + lr) * 128 + kin * 2));
                LDSM4(af[mf][0], af[mf][1], af[mf][2], af[mf][3], sA + off);
            }
#pragma unroll
            for (int nf = 0; nf < 2; nf++) {
                uint32_t off = hoffB + SW128((uint32_t)((wn * 32 + nf * 16 + lr) * 128 + kin * 2));
                LDSM4(b1f[nf][0], b1f[nf][1], b1f[nf][2], b1f[nf][3], sB1 + off);
                LDSM4(b2f[nf][0], b2f[nf][1], b2f[nf][2], b2f[nf][3], sB2 + off);
            }
#pragma unroll
            for (int mf = 0; mf < 2; mf++) {
#pragma unroll
                for (int ns = 0; ns < 4; ns++) {
                    int g = ns >> 1, od = ns & 1;
                    uint32_t bb1[2] = { b1f[g][od], b1f[g][od + 2] };
                    uint32_t bb2[2] = { b2f[g][od], b2f[g][od + 2] };
                    mma16816(acc1[mf][ns], af[mf], bb1);
                    mma16816(acc2[mf][ns], af[mf], bb2);
                }
            }
        }
    }

    int qrow = lane >> 2, qcol = (lane & 3) * 2;
#pragma unroll
    for (int mf = 0; mf < 2; mf++) {
#pragma unroll
        for (int ns = 0; ns < 4; ns++) {
            int r0 = row0 + wm * 32 + mf * 16 + qrow;
            int c0 = wn * 32 + ns * 8 + qcol;
            if (r0 < n) {
                __half2 h1 = __floats2half2_rn(acc1[mf][ns][0], acc1[mf][ns][1]);
                __half2 h2 = __floats2half2_rn(acc2[mf][ns][0], acc2[mf][ns][1]);
                *reinterpret_cast<uint32_t*>(&C1[(size_t)r0 * 128 + c0]) = *(uint32_t*)&h1;
                *reinterpret_cast<uint32_t*>(&C2[(size_t)r0 * 128 + c0]) = *(uint32_t*)&h2;
            }
            if (r0 + 8 < n) {
                __half2 h1 = __floats2half2_rn(acc1[mf][ns][2], acc1[mf][ns][3]);
                __half2 h2 = __floats2half2_rn(acc2[mf][ns][2], acc2[mf][ns][3]);
                *reinterpret_cast<uint32_t*>(&C1[(size_t)(r0 + 8) * 128 + c0]) = *(uint32_t*)&h1;
                *reinterpret_cast<uint32_t*>(&C2[(size_t)(r0 + 8) * 128 + c0]) = *(uint32_t*)&h2;
            }
        }
    }
}

// ---------------- warp helpers ----------------
__device__ __forceinline__ float warp_sum(float v) {
#pragma unroll
    for (int o = 16; o; o >>= 1) v += __shfl_xor_sync(0xffffffffu, v, o);
    return v;
}

__device__ __forceinline__ float lrelu(float x) { return x >= 0.f ? x : 0.2f * x; }
__device__ __forceinline__ float elu(float x)  { return x > 0.f ? x : expm1f(x); }

// ---------------- fused GAT aggregation ----------------
__global__ void k_edgeagg(const __half* __restrict__ h,
                          const float* __restrict__ xprev_f,
                          __half* __restrict__ x, int n)
{
    __shared__ int   sidx[8][32];
    __shared__ float4 swt[8][32];

    int w = threadIdx.x >> 5;
    int gw = (blockIdx.x * blockDim.x + threadIdx.x) >> 5;
    int lane = threadIdx.x & 31;
    if (gw >= n) return;

    int base = g_rowptr[gw];
    int deg  = g_rowptr[gw + 1] - base;
    float4 ad = g_adst[gw];
    float4 acc = make_float4(0.f, 0.f, 0.f, 0.f);
    int hsel = lane >> 3;

    if (deg <= 32) {
        int myidx = 0;
        float p0 = 0.f, p1 = 0.f, p2 = 0.f, p3 = 0.f;
        if (lane < deg) {
            myidx = g_col[base + lane];
            float4 as = g_asrc[myidx];
            p0 = expf(fminf(lrelu(as.x + ad.x), 75.f));
            p1 = expf(fminf(lrelu(as.y + ad.y), 75.f));
            p2 = expf(fminf(lrelu(as.z + ad.z), 75.f));
            p3 = expf(fminf(lrelu(as.w + ad.w), 75.f));
        }
        float i0 = 1.f / (warp_sum(p0) + 1e-10f);
        float i1 = 1.f / (warp_sum(p1) + 1e-10f);
        float i2 = 1.f / (warp_sum(p2) + 1e-10f);
        float i3 = 1.f / (warp_sum(p3) + 1e-10f);
        sidx[w][lane] = myidx;
        swt[w][lane] = make_float4(p0 * i0, p1 * i1, p2 * i2, p3 * i3);
        __syncwarp();
#pragma unroll 4
        for (int j = 0; j < deg; j++) {
            int s = sidx[w][j];
            float wj = reinterpret_cast<const float*>(&swt[w][j])[hsel];
            uint2 raw = *reinterpret_cast<const uint2*>(&h[(size_t)s * 128 + 4 * lane]);
            float2 f01 = __half22float2(*reinterpret_cast<const __half2*>(&raw.x));
            float2 f23 = __half22float2(*reinterpret_cast<const __half2*>(&raw.y));
            acc.x += f01.x * wj;
            acc.y += f01.y * wj;
            acc.z += f23.x * wj;
            acc.w += f23.y * wj;
        }
    } else {
        float s0 = 0.f, s1 = 0.f, s2 = 0.f, s3 = 0.f;
        for (int i = lane; i < deg; i += 32) {
            int s = g_col[base + i];
            float4 as = g_asrc[s];
            float p0 = expf(fminf(lrelu(as.x + ad.x), 75.f));
            float p1 = expf(fminf(lrelu(as.y + ad.y), 75.f));
            float p2 = expf(fminf(lrelu(as.z + ad.z), 75.f));
            float p3 = expf(fminf(lrelu(as.w + ad.w), 75.f));
            g_ew[base + i] = make_float4(p0, p1, p2, p3);
            s0 += p0; s1 += p1; s2 += p2; s3 += p3;
        }
        s0 = warp_sum(s0); s1 = warp_sum(s1); s2 = warp_sum(s2); s3 = warp_sum(s3);
        float i0 = 1.f / (s0 + 1e-10f);
        float i1 = 1.f / (s1 + 1e-10f);
        float i2 = 1.f / (s2 + 1e-10f);
        float i3 = 1.f / (s3 + 1e-10f);

        for (int bi = 0; bi < deg; bi += 32) {
            int cnt = min(32, deg - bi);
            if (lane < cnt) {
                sidx[w][lane] = g_col[base + bi + lane];
                float4 p = g_ew[base + bi + lane];
                swt[w][lane] = make_float4(p.x * i0, p.y * i1, p.z * i2, p.w * i3);
            }
            __syncwarp();
#pragma unroll 4
            for (int j = 0; j < cnt; j++) {
                int s = sidx[w][j];
                float wj = reinterpret_cast<const float*>(&swt[w][j])[hsel];
                uint2 raw = *reinterpret_cast<const uint2*>(&h[(size_t)s * 128 + 4 * lane]);
                float2 f01 = __half22float2(*reinterpret_cast<const __half2*>(&raw.x));
                float2 f23 = __half22float2(*reinterpret_cast<const __half2*>(&raw.y));
                acc.x += f01.x * wj;
                acc.y += f01.y * wj;
                acc.z += f23.x * wj;
                acc.w += f23.y * wj;
            }
            __syncwarp();
        }
    }

    size_t o = (size_t)gw * 128 + 4 * lane;
    float4 xp;
    if (xprev_f) {
        xp = *reinterpret_cast<const float4*>(&xprev_f[o]);
    } else {
        uint2 rx = *reinterpret_cast<const uint2*>(&x[o]);
        float2 x01 = __half22float2(*reinterpret_cast<const __half2*>(&rx.x));
        float2 x23 = __half22float2(*reinterpret_cast<const __half2*>(&rx.y));
        xp = make_float4(x01.x, x01.y, x23.x, x23.y);
    }
    float4 v = make_float4(elu(acc.x) + xp.x, elu(acc.y) + xp.y,
                           elu(acc.z) + xp.z, elu(acc.w) + xp.w);
    {
        __half2 h0 = __floats2half2_rn(v.x, v.y);
        __half2 h1 = __floats2half2_rn(v.z, v.w);
        uint2 pv = make_uint2(*(uint32_t*)&h0, *(uint32_t*)&h1);
        *reinterpret_cast<uint2*>(&x[o]) = pv;
    }
}

// ---------------- pair epilogue ----------------
__global__ void k_pairs(const int* __restrict__ lsrc, const int* __restrict__ ldst,
                        const float* __restrict__ b1, const float* __restrict__ w2,
                        const float* __restrict__ b2, float* __restrict__ out, int p)
{
    int gw = (blockIdx.x * blockDim.x + threadIdx.x) >> 5;
    int lane = threadIdx.x & 31;
    if (gw >= p) return;
    int k = 4 * lane;
    uint2 ru = *reinterpret_cast<const uint2*>(&g_u[(size_t)lsrc[gw] * 128 + k]);
    uint2 rv = *reinterpret_cast<const uint2*>(&g_v[(size_t)ldst[gw] * 128 + k]);
    float2 u01 = __half22float2(*reinterpret_cast<const __half2*>(&ru.x));
    float2 u23 = __half22float2(*reinterpret_cast<const __half2*>(&ru.y));
    float2 v01 = __half22float2(*reinterpret_cast<const __half2*>(&rv.x));
    float2 v23 = __half22float2(*reinterpret_cast<const __half2*>(&rv.y));
    float4 b = *reinterpret_cast<const float4*>(&b1[k]);
    float4 w = *reinterpret_cast<const float4*>(&w2[k]);
    float t = fmaxf(u01.x + v01.x + b.x, 0.f) * w.x
            + fmaxf(u01.y + v01.y + b.y, 0.f) * w.y
            + fmaxf(u23.x + v23.x + b.z, 0.f) * w.z
            + fmaxf(u23.y + v23.y + b.w, 0.f) * w.w;
    t = warp_sum(t);
    if (lane == 0) out[gw] = t + b2[0];
}

// ---------------- driver ----------------
extern "C" void kernel_launch(void* const* d_in, const int* in_sizes, int n_in,
                              void* d_out, int out_size)
{
    const float* embed  = (const float*)d_in[0];
    const float* W1     = (const float*)d_in[1];
    const float* a_src1 = (const float*)d_in[2];
    const float* a_dst1 = (const float*)d_in[3];
    const float* W2     = (const float*)d_in[4];
    const float* a_src2 = (const float*)d_in[5];
    const float* a_dst2 = (const float*)d_in[6];
    const float* lp_w1  = (const float*)d_in[7];
    const float* lp_b1  = (const float*)d_in[8];
    const float* lp_w2  = (const float*)d_in[9];
    const float* lp_b2  = (const float*)d_in[10];
    const int*   eidx   = (const int*)d_in[11];
    const int*   lsrc   = (const int*)d_in[12];
    const int*   ldst   = (const int*)d_in[13];
    float* out = (float*)d_out;

    const int N = in_sizes[0] / DDIM;
    const int E = in_sizes[11] / 2;
    const int P = in_sizes[12];
    const int* esrc = eidx;
    const int* edst = eidx + E;

    __half* hbuf; cudaGetSymbolAddress((void**)&hbuf, g_h);
    __half* xbuf; cudaGetSymbolAddress((void**)&xbuf, g_x);
    __half* ub;   cudaGetSymbolAddress((void**)&ub,   g_u);
    __half* vb;   cudaGetSymbolAddress((void**)&vb,   g_v);
    __half* wt;   cudaGetSymbolAddress((void**)&wt,   g_wt);

    cudaFuncSetAttribute(k_gemm_mma,  cudaFuncAttributeMaxDynamicSharedMemorySize, GEMM_SMEM);
    cudaFuncSetAttribute(k_gemm_mma2, cudaFuncAttributeMaxDynamicSharedMemorySize, GEMM2_SMEM);

    const int T = 256;
    int nbN  = (N + T - 1) / T;
    int nbE  = (E + T - 1) / T;
    int nbS  = (N + 1023) / 1024;
    int nbW  = (N * 32 + T - 1) / T;
    int nbPW = (P * 32 + T - 1) / T;
    int nbG  = (N + 63) / 64;
    const int WSZ = DDIM * DDIM;

    k_setup<<<nbN, T>>>(W1, W2, lp_w1, wt, N);              // 0
    k_hist<<<nbE, T>>>(edst, E);                            // 1
    k_scan1<<<nbS, 1024>>>(N);                              // 2
    k_gemm_mma<<<nbG, 256, GEMM_SMEM>>>(embed, nullptr,     // 3 (profiled)
                                        wt + 0 * WSZ, hbuf, a_src1, a_dst1, N);
    k_scan2<<<1, 128>>>(nbS);                               // 4
    k_scan3<<<nbS, 1024>>>(N, E);                           // 5
    k_scatter<<<nbE, T>>>(esrc, edst, E);                   // 6

    k_edgeagg<<<nbW, T>>>(hbuf, embed, xbuf, N);            // 7

    k_gemm_mma<<<nbG, 256, GEMM_SMEM>>>(nullptr, xbuf,      // 8
                                        wt + 1 * WSZ, hbuf, a_src2, a_dst2, N);
    k_edgeagg<<<nbW, T>>>(hbuf, nullptr, xbuf, N);          // 9

    k_gemm_mma2<<<nbG, 256, GEMM2_SMEM>>>(xbuf,             // 10
                                          wt + 2 * WSZ, wt + 3 * WSZ,
                                          ub, vb, N);
    k_pairs<<<nbPW, T>>>(lsrc, ldst, lp_b1, lp_w2, lp_b2, out, P);  // 11
}